// round 2
// baseline (speedup 1.0000x reference)
#include <cuda_runtime.h>
#include <cstdint>

#define BATCH 4
#define SEQ 2048
#define DIM 512
#define DSTATE 16
#define DCONV 4
#define DINNER 1024
#define DTRANK 32
#define NTOK (BATCH*SEQ)   // 8192

// ---------------- scratch (device globals: allocation-free) ----------------
__device__ float g_w  [(size_t)NTOK*DIM];     // layernorm output
__device__ float g_xm [(size_t)NTOK*DINNER];  // in-proj first half
__device__ float g_z  [(size_t)NTOK*DINNER];  // in-proj second half (gate)
__device__ float g_xc [(size_t)NTOK*DINNER];  // conv+silu output
__device__ float g_dbc[(size_t)NTOK*64];      // xproj output (dt_in|B|C)
__device__ float g_dt [(size_t)NTOK*DINNER];  // softplus(dt)
__device__ float g_y  [(size_t)NTOK*DINNER];  // gated scan output

// ---------------- layernorm ----------------
__global__ void ln_kernel(const float* __restrict__ x, const float* __restrict__ g,
                          const float* __restrict__ b) {
    int row = blockIdx.x;
    const float* xr = x + (size_t)row * DIM;
    int tid = threadIdx.x;                    // 256 threads, 2 elems each
    float v0 = xr[tid], v1 = xr[tid + 256];
    float s = v0 + v1, q = v0*v0 + v1*v1;
    __shared__ float ss[8], sq[8];
    #pragma unroll
    for (int o = 16; o > 0; o >>= 1) {
        s += __shfl_down_sync(0xffffffffu, s, o);
        q += __shfl_down_sync(0xffffffffu, q, o);
    }
    if ((tid & 31) == 0) { ss[tid >> 5] = s; sq[tid >> 5] = q; }
    __syncthreads();
    __shared__ float mean_s, rstd_s;
    if (tid == 0) {
        float st = 0.f, qt = 0.f;
        #pragma unroll
        for (int i = 0; i < 8; i++) { st += ss[i]; qt += sq[i]; }
        float m = st / DIM;
        float var = qt / DIM - m*m;
        mean_s = m;
        rstd_s = rsqrtf(var + 1e-5f);
    }
    __syncthreads();
    float m = mean_s, r = rstd_s;
    g_w[(size_t)row*DIM + tid]       = (v0 - m)*r*g[tid]       + b[tid];
    g_w[(size_t)row*DIM + tid + 256] = (v1 - m)*r*g[tid + 256] + b[tid + 256];
}

// ---------------- in-proj GEMM: g_w[8192x512] @ in_w[512x2048] -> g_xm|g_z -------
// BM=128 BN=128 BK=16, 256 threads, 8x8 per thread. flip folds the time reversal
// for the backward direction into the A-row gather.
__global__ __launch_bounds__(256) void gemm_in_kernel(const float* __restrict__ Bw, int flip) {
    const int K = DIM, N = 2*DINNER;
    __shared__ float As[16][132];
    __shared__ float Bs[16][128];
    int bm = blockIdx.y * 128;
    int bn = blockIdx.x * 128;
    int tid = threadIdx.x;
    int tr = tid >> 4, tc = tid & 15;
    float acc[8][8] = {};
    for (int k0 = 0; k0 < K; k0 += 16) {
        #pragma unroll
        for (int i = 0; i < 2; i++) {
            int id = tid + i*256;
            int row = id >> 2, c4 = (id & 3) << 2;
            int grow = bm + row;
            int srow = flip ? ((grow & ~(SEQ-1)) + (SEQ-1 - (grow & (SEQ-1)))) : grow;
            float4 v = *(const float4*)(g_w + (size_t)srow*K + k0 + c4);
            As[c4][row] = v.x; As[c4+1][row] = v.y; As[c4+2][row] = v.z; As[c4+3][row] = v.w;
        }
        #pragma unroll
        for (int i = 0; i < 2; i++) {
            int id = tid + i*256;
            int row = id >> 5, c4 = (id & 31) << 2;
            *(float4*)&Bs[row][c4] = *(const float4*)(Bw + (size_t)(k0+row)*N + bn + c4);
        }
        __syncthreads();
        #pragma unroll
        for (int k = 0; k < 16; k++) {
            float4 a0 = *(const float4*)&As[k][tr*8];
            float4 a1 = *(const float4*)&As[k][tr*8 + 4];
            float4 b0 = *(const float4*)&Bs[k][tc*8];
            float4 b1 = *(const float4*)&Bs[k][tc*8 + 4];
            float a[8] = {a0.x,a0.y,a0.z,a0.w,a1.x,a1.y,a1.z,a1.w};
            float b[8] = {b0.x,b0.y,b0.z,b0.w,b1.x,b1.y,b1.z,b1.w};
            #pragma unroll
            for (int i = 0; i < 8; i++)
                #pragma unroll
                for (int j = 0; j < 8; j++) acc[i][j] = fmaf(a[i], b[j], acc[i][j]);
        }
        __syncthreads();
    }
    #pragma unroll
    for (int i = 0; i < 8; i++) {
        int m = bm + tr*8 + i;
        #pragma unroll
        for (int j = 0; j < 8; j += 4) {
            int n = bn + tc*8 + j;
            float4 v = {acc[i][j], acc[i][j+1], acc[i][j+2], acc[i][j+3]};
            if (n < DINNER) *(float4*)&g_xm[(size_t)m*DINNER + n] = v;
            else            *(float4*)&g_z [(size_t)m*DINNER + n - DINNER] = v;
        }
    }
}

// ---------------- causal depthwise conv (k=4) + SiLU ----------------
__global__ void conv_kernel(const float* __restrict__ cw, const float* __restrict__ cb) {
    size_t idx = (size_t)blockIdx.x * blockDim.x + threadIdx.x;
    int d = (int)(idx & (DINNER-1));
    int t = (int)((idx >> 10) & (SEQ-1));
    float acc = cb[d];
    #pragma unroll
    for (int k = 0; k < DCONV; k++) {
        int ts = t + k - (DCONV-1);
        if (ts >= 0)
            acc = fmaf(g_xm[idx + (size_t)((long)k - (DCONV-1)) * DINNER], cw[k*DINNER + d], acc);
    }
    float sg = 1.f / (1.f + __expf(-acc));
    g_xc[idx] = acc * sg;
}

// ---------------- xproj GEMM: g_xc[8192x1024] @ xproj_w[1024x64] -> g_dbc --------
// BM=64 BN=64 BK=16, 256 threads, 4x4 per thread.
__global__ __launch_bounds__(256) void xproj_kernel(const float* __restrict__ Bw) {
    __shared__ float As[16][68];
    __shared__ float Bs[16][64];
    int bm = blockIdx.x * 64;
    int tid = threadIdx.x;
    int tr = tid >> 4, tc = tid & 15;
    float acc[4][4] = {};
    for (int k0 = 0; k0 < DINNER; k0 += 16) {
        {
            int row = tid >> 2, c4 = (tid & 3) << 2;
            float4 v = *(const float4*)(g_xc + (size_t)(bm+row)*DINNER + k0 + c4);
            As[c4][row] = v.x; As[c4+1][row] = v.y; As[c4+2][row] = v.z; As[c4+3][row] = v.w;
        }
        {
            int row = tid >> 4, c4 = (tid & 15) << 2;
            *(float4*)&Bs[row][c4] = *(const float4*)(Bw + (size_t)(k0+row)*64 + c4);
        }
        __syncthreads();
        #pragma unroll
        for (int k = 0; k < 16; k++) {
            float a[4], b[4];
            *(float4*)a = *(const float4*)&As[k][tr*4];
            *(float4*)b = *(const float4*)&Bs[k][tc*4];
            #pragma unroll
            for (int i = 0; i < 4; i++)
                #pragma unroll
                for (int j = 0; j < 4; j++) acc[i][j] = fmaf(a[i], b[j], acc[i][j]);
        }
        __syncthreads();
    }
    #pragma unroll
    for (int i = 0; i < 4; i++) {
        int m = bm + tr*4 + i;
        float4 v = {acc[i][0], acc[i][1], acc[i][2], acc[i][3]};
        *(float4*)&g_dbc[(size_t)m*64 + tc*4] = v;
    }
}

// ---------------- dt GEMM (K=32) + bias + softplus ----------------
// 1024 threads = one per output channel, weights register-cached, 16 rows/block.
__global__ __launch_bounds__(1024) void dt_kernel(const float* __restrict__ dtw,
                                                  const float* __restrict__ dtb) {
    const int ROWS = 16;
    int m0 = blockIdx.x * ROWS;
    int n = threadIdx.x;
    __shared__ float s[ROWS][DTRANK];
    if (n < ROWS*DTRANK) {
        int r = n >> 5, k = n & 31;
        s[r][k] = g_dbc[(size_t)(m0+r)*64 + k];
    }
    __syncthreads();
    float w[32];
    #pragma unroll
    for (int k = 0; k < 32; k++) w[k] = dtw[k*DINNER + n];
    float bias = dtb[n];
    #pragma unroll 4
    for (int r = 0; r < ROWS; r++) {
        float acc = bias;
        #pragma unroll
        for (int k = 0; k < 32; k++) acc = fmaf(s[r][k], w[k], acc);
        float v = (acc > 20.f) ? acc : log1pf(__expf(acc));
        g_dt[(size_t)(m0+r)*DINNER + n] = v;
    }
}

// ---------------- selective scan + Dp skip + SiLU(z) gate ----------------
// one thread per (b, d) channel; 16 states in registers; B/C double-buffered in smem.
__global__ __launch_bounds__(64) void scan_kernel(const float* __restrict__ A_log,
                                                  const float* __restrict__ Dp) {
    int b = blockIdx.x;
    int d = blockIdx.y * 64 + threadIdx.x;
    int tid = threadIdx.x;
    float a[DSTATE], h[DSTATE];
    #pragma unroll
    for (int s = 0; s < DSTATE; s++) {
        a[s] = -__expf(A_log[(size_t)d*DSTATE + s]);
        h[s] = 0.f;
    }
    float Dv = Dp[d];
    __shared__ float sBC[2][32];
    size_t base  = (size_t)b * SEQ * DINNER + d;
    size_t cbase = (size_t)b * SEQ * 64;
    for (int t = 0; t < SEQ; t++) {
        int cur = t & 1;
        if (tid < 32) sBC[cur][tid] = g_dbc[cbase + (size_t)t*64 + 32 + tid];
        __syncthreads();
        size_t off = base + (size_t)t * DINNER;
        float dtv = g_dt[off];
        float xv  = g_xc[off];
        float zv  = g_z[off];
        float dtx = dtv * xv;
        float yv = 0.f;
        #pragma unroll
        for (int s = 0; s < DSTATE; s++) {
            float r = __expf(dtv * a[s]);
            h[s] = fmaf(r, h[s], dtx * sBC[cur][s]);
            yv = fmaf(h[s], sBC[cur][16 + s], yv);
        }
        float sg = 1.f / (1.f + __expf(-zv));
        g_y[off] = (yv + xv * Dv) * (zv * sg);
    }
}

// ---------------- out-proj GEMM + residual combine ----------------
// g_y[8192x1024] @ out_w[1024x512]; dir0: out = x + 0.5*acc; dir1: out += 0.5*acc
// at the time-flipped row.
__global__ __launch_bounds__(256) void gemm_out_kernel(const float* __restrict__ Bw,
                                                       const float* __restrict__ x,
                                                       float* __restrict__ out, int dir) {
    const int K = DINNER, N = DIM;
    __shared__ float As[16][132];
    __shared__ float Bs[16][128];
    int bm = blockIdx.y * 128;
    int bn = blockIdx.x * 128;
    int tid = threadIdx.x;
    int tr = tid >> 4, tc = tid & 15;
    float acc[8][8] = {};
    for (int k0 = 0; k0 < K; k0 += 16) {
        #pragma unroll
        for (int i = 0; i < 2; i++) {
            int id = tid + i*256;
            int row = id >> 2, c4 = (id & 3) << 2;
            float4 v = *(const float4*)(g_y + (size_t)(bm+row)*K + k0 + c4);
            As[c4][row] = v.x; As[c4+1][row] = v.y; As[c4+2][row] = v.z; As[c4+3][row] = v.w;
        }
        #pragma unroll
        for (int i = 0; i < 2; i++) {
            int id = tid + i*256;
            int row = id >> 5, c4 = (id & 31) << 2;
            *(float4*)&Bs[row][c4] = *(const float4*)(Bw + (size_t)(k0+row)*N + bn + c4);
        }
        __syncthreads();
        #pragma unroll
        for (int k = 0; k < 16; k++) {
            float4 a0 = *(const float4*)&As[k][tr*8];
            float4 a1 = *(const float4*)&As[k][tr*8 + 4];
            float4 b0 = *(const float4*)&Bs[k][tc*8];
            float4 b1 = *(const float4*)&Bs[k][tc*8 + 4];
            float a[8] = {a0.x,a0.y,a0.z,a0.w,a1.x,a1.y,a1.z,a1.w};
            float b[8] = {b0.x,b0.y,b0.z,b0.w,b1.x,b1.y,b1.z,b1.w};
            #pragma unroll
            for (int i = 0; i < 8; i++)
                #pragma unroll
                for (int j = 0; j < 8; j++) acc[i][j] = fmaf(a[i], b[j], acc[i][j]);
        }
        __syncthreads();
    }
    #pragma unroll
    for (int i = 0; i < 8; i++) {
        int m = bm + tr*8 + i;
        int t = m & (SEQ-1);
        int grow = (m & ~(SEQ-1)) + (dir ? (SEQ-1 - t) : t);
        #pragma unroll
        for (int j = 0; j < 8; j += 4) {
            int n = bn + tc*8 + j;
            float4 v = {0.5f*acc[i][j], 0.5f*acc[i][j+1], 0.5f*acc[i][j+2], 0.5f*acc[i][j+3]};
            float* op = out + (size_t)grow*DIM + n;
            if (dir == 0) {
                float4 xv = *(const float4*)(x + (size_t)grow*DIM + n);
                v.x += xv.x; v.y += xv.y; v.z += xv.z; v.w += xv.w;
            } else {
                float4 ov = *(const float4*)op;
                v.x += ov.x; v.y += ov.y; v.z += ov.z; v.w += ov.w;
            }
            *(float4*)op = v;
        }
    }
}

// ---------------- launch ----------------
extern "C" void kernel_launch(void* const* d_in, const int* in_sizes, int n_in,
                              void* d_out, int out_size) {
    const float* x    = (const float*)d_in[0];
    const float* ln_g = (const float*)d_in[1];
    const float* ln_b = (const float*)d_in[2];

    ln_kernel<<<NTOK, 256>>>(x, ln_g, ln_b);

    for (int dir = 0; dir < 2; dir++) {
        const float* in_w    = (const float*)d_in[3 + 9*dir + 0];
        const float* conv_w  = (const float*)d_in[3 + 9*dir + 1];
        const float* conv_b  = (const float*)d_in[3 + 9*dir + 2];
        const float* xproj_w = (const float*)d_in[3 + 9*dir + 3];
        const float* dt_w    = (const float*)d_in[3 + 9*dir + 4];
        const float* dt_b    = (const float*)d_in[3 + 9*dir + 5];
        const float* A_log   = (const float*)d_in[3 + 9*dir + 6];
        const float* Dp      = (const float*)d_in[3 + 9*dir + 7];
        const float* out_w   = (const float*)d_in[3 + 9*dir + 8];

        gemm_in_kernel<<<dim3(2*DINNER/128, NTOK/128), 256>>>(in_w, dir);
        conv_kernel<<<(NTOK*(size_t)DINNER)/256, 256>>>(conv_w, conv_b);
        xproj_kernel<<<NTOK/64, 256>>>(xproj_w);
        dt_kernel<<<NTOK/16, 1024>>>(dt_w, dt_b);
        scan_kernel<<<dim3(BATCH, DINNER/64), 64>>>(A_log, Dp);
        gemm_out_kernel<<<dim3(DIM/128, NTOK/128), 256>>>(out_w, x, (float*)d_out, dir);
    }
}

// round 3
// speedup vs baseline: 1.4670x; 1.4670x over previous
#include <cuda_runtime.h>
#include <cstdint>

#define BATCH 4
#define SEQ 2048
#define DIM 512
#define DSTATE 16
#define DCONV 4
#define DINNER 1024
#define DTRANK 32
#define NTOK (BATCH*SEQ)   // 8192
#define FULLMASK 0xffffffffu

// ---------------- packed f32x2 helpers (sm_100a) ----------------
#define PACK2(out, lo, hi) asm("mov.b64 %0, {%1, %2};" : "=l"(out) : "f"(lo), "f"(hi))
#define UNPACK2(lo, hi, v) asm("mov.b64 {%0, %1}, %2;" : "=f"(lo), "=f"(hi) : "l"(v))
#define FMUL2(d, a, b)     asm("mul.rn.f32x2 %0, %1, %2;" : "=l"(d) : "l"(a), "l"(b))
#define FFMA2(d, a, b, c)  asm("fma.rn.f32x2 %0, %1, %2, %3;" : "=l"(d) : "l"(a), "l"(b), "l"(c))

// ---------------- scratch (device globals: allocation-free) ----------------
__device__ float g_w  [(size_t)NTOK*DIM];     // layernorm output
__device__ float g_xm [(size_t)NTOK*DINNER];  // in-proj first half
__device__ float g_z  [(size_t)NTOK*DINNER];  // in-proj second half (gate)
__device__ float g_xc [(size_t)NTOK*DINNER];  // conv+silu output
__device__ float g_dbc[(size_t)NTOK*64];      // xproj output (dt_in|B|C)
__device__ float g_dt [(size_t)NTOK*DINNER];  // softplus(dt)
__device__ float g_y  [(size_t)NTOK*DINNER];  // gated scan output

// ---------------- layernorm ----------------
__global__ void ln_kernel(const float* __restrict__ x, const float* __restrict__ g,
                          const float* __restrict__ b) {
    int row = blockIdx.x;
    const float* xr = x + (size_t)row * DIM;
    int tid = threadIdx.x;                    // 256 threads, 2 elems each
    float v0 = xr[tid], v1 = xr[tid + 256];
    float s = v0 + v1, q = v0*v0 + v1*v1;
    __shared__ float ss[8], sq[8];
    #pragma unroll
    for (int o = 16; o > 0; o >>= 1) {
        s += __shfl_down_sync(FULLMASK, s, o);
        q += __shfl_down_sync(FULLMASK, q, o);
    }
    if ((tid & 31) == 0) { ss[tid >> 5] = s; sq[tid >> 5] = q; }
    __syncthreads();
    __shared__ float mean_s, rstd_s;
    if (tid == 0) {
        float st = 0.f, qt = 0.f;
        #pragma unroll
        for (int i = 0; i < 8; i++) { st += ss[i]; qt += sq[i]; }
        float m = st / DIM;
        float var = qt / DIM - m*m;
        mean_s = m;
        rstd_s = rsqrtf(var + 1e-5f);
    }
    __syncthreads();
    float m = mean_s, r = rstd_s;
    g_w[(size_t)row*DIM + tid]       = (v0 - m)*r*g[tid]       + b[tid];
    g_w[(size_t)row*DIM + tid + 256] = (v1 - m)*r*g[tid + 256] + b[tid + 256];
}

// ---------------- in-proj GEMM (double-buffered) --------------------------
// g_w[8192x512] @ in_w[512x2048] -> g_xm | g_z. flip folds backward-direction
// time reversal into the A-row gather.
__global__ __launch_bounds__(256) void gemm_in_kernel(const float* __restrict__ Bw, int flip) {
    const int K = DIM, N = 2*DINNER, KT = K/16;
    __shared__ float As[2][16][132];
    __shared__ float Bs[2][16][128];
    int bm = blockIdx.y * 128;
    int bn = blockIdx.x * 128;
    int tid = threadIdx.x;
    int tr = tid >> 4, tc = tid & 15;
    int arow0 = tid >> 2, ac4 = (tid & 3) << 2;

    float4 ra[2], rb[2];
    auto loadT = [&](int k0) {
        #pragma unroll
        for (int i = 0; i < 2; i++) {
            int grow = bm + arow0 + i*64;
            int srow = flip ? ((grow & ~(SEQ-1)) + (SEQ-1 - (grow & (SEQ-1)))) : grow;
            ra[i] = *(const float4*)(g_w + (size_t)srow*K + k0 + ac4);
        }
        #pragma unroll
        for (int i = 0; i < 2; i++) {
            int id = tid + i*256;
            int row = id >> 5, c4 = (id & 31) << 2;
            rb[i] = *(const float4*)(Bw + (size_t)(k0+row)*N + bn + c4);
        }
    };
    auto storeT = [&](int buf) {
        #pragma unroll
        for (int i = 0; i < 2; i++) {
            int row = arow0 + i*64;
            As[buf][ac4][row]   = ra[i].x; As[buf][ac4+1][row] = ra[i].y;
            As[buf][ac4+2][row] = ra[i].z; As[buf][ac4+3][row] = ra[i].w;
        }
        #pragma unroll
        for (int i = 0; i < 2; i++) {
            int id = tid + i*256;
            int row = id >> 5, c4 = (id & 31) << 2;
            *(float4*)&Bs[buf][row][c4] = rb[i];
        }
    };

    float acc[8][8] = {};
    loadT(0); storeT(0); __syncthreads();
    if (KT > 1) loadT(16);
    for (int kt = 0; kt < KT; kt++) {
        int cur = kt & 1;
        if (kt + 1 < KT) storeT(cur ^ 1);
        if (kt + 2 < KT) loadT((kt + 2) * 16);
        #pragma unroll
        for (int k = 0; k < 16; k++) {
            float av[8], bv[8];
            *(float4*)&av[0] = *(const float4*)&As[cur][k][tr*8];
            *(float4*)&av[4] = *(const float4*)&As[cur][k][tr*8 + 4];
            *(float4*)&bv[0] = *(const float4*)&Bs[cur][k][tc*8];
            *(float4*)&bv[4] = *(const float4*)&Bs[cur][k][tc*8 + 4];
            #pragma unroll
            for (int i = 0; i < 8; i++)
                #pragma unroll
                for (int j = 0; j < 8; j++) acc[i][j] = fmaf(av[i], bv[j], acc[i][j]);
        }
        __syncthreads();
    }
    #pragma unroll
    for (int i = 0; i < 8; i++) {
        int m = bm + tr*8 + i;
        #pragma unroll
        for (int j = 0; j < 8; j += 4) {
            int n = bn + tc*8 + j;
            float4 v = {acc[i][j], acc[i][j+1], acc[i][j+2], acc[i][j+3]};
            if (n < DINNER) *(float4*)&g_xm[(size_t)m*DINNER + n] = v;
            else            *(float4*)&g_z [(size_t)m*DINNER + n - DINNER] = v;
        }
    }
}

// ---------------- causal depthwise conv (k=4) + SiLU ----------------
__global__ void conv_kernel(const float* __restrict__ cw, const float* __restrict__ cb) {
    size_t idx = (size_t)blockIdx.x * blockDim.x + threadIdx.x;
    int d = (int)(idx & (DINNER-1));
    int t = (int)((idx >> 10) & (SEQ-1));
    float acc = cb[d];
    #pragma unroll
    for (int k = 0; k < DCONV; k++) {
        int ts = t + k - (DCONV-1);
        if (ts >= 0)
            acc = fmaf(g_xm[idx + (size_t)((long)k - (DCONV-1)) * DINNER], cw[k*DINNER + d], acc);
    }
    float sg = 1.f / (1.f + __expf(-acc));
    g_xc[idx] = acc * sg;
}

// ---------------- xproj GEMM (double-buffered) ----------------------------
// g_xc[8192x1024] @ xproj_w[1024x64] -> g_dbc
__global__ __launch_bounds__(256) void xproj_kernel(const float* __restrict__ Bw) {
    const int KT = DINNER/16;
    __shared__ float As[2][16][68];
    __shared__ float Bs[2][16][64];
    int bm = blockIdx.x * 64;
    int tid = threadIdx.x;
    int tr = tid >> 4, tc = tid & 15;
    int arow = tid >> 2, ac4 = (tid & 3) << 2;
    int brow = tid >> 4, bc4 = (tid & 15) << 2;

    float4 ra, rb;
    auto loadT = [&](int k0) {
        ra = *(const float4*)(g_xc + (size_t)(bm+arow)*DINNER + k0 + ac4);
        rb = *(const float4*)(Bw + (size_t)(k0+brow)*64 + bc4);
    };
    auto storeT = [&](int buf) {
        As[buf][ac4][arow]   = ra.x; As[buf][ac4+1][arow] = ra.y;
        As[buf][ac4+2][arow] = ra.z; As[buf][ac4+3][arow] = ra.w;
        *(float4*)&Bs[buf][brow][bc4] = rb;
    };

    float acc[4][4] = {};
    loadT(0); storeT(0); __syncthreads();
    loadT(16);
    for (int kt = 0; kt < KT; kt++) {
        int cur = kt & 1;
        if (kt + 1 < KT) storeT(cur ^ 1);
        if (kt + 2 < KT) loadT((kt + 2) * 16);
        #pragma unroll
        for (int k = 0; k < 16; k++) {
            float a[4], b[4];
            *(float4*)a = *(const float4*)&As[cur][k][tr*4];
            *(float4*)b = *(const float4*)&Bs[cur][k][tc*4];
            #pragma unroll
            for (int i = 0; i < 4; i++)
                #pragma unroll
                for (int j = 0; j < 4; j++) acc[i][j] = fmaf(a[i], b[j], acc[i][j]);
        }
        __syncthreads();
    }
    #pragma unroll
    for (int i = 0; i < 4; i++) {
        int m = bm + tr*4 + i;
        float4 v = {acc[i][0], acc[i][1], acc[i][2], acc[i][3]};
        *(float4*)&g_dbc[(size_t)m*64 + tc*4] = v;
    }
}

// ---------------- dt GEMM (K=32) + bias + softplus ----------------
__global__ __launch_bounds__(1024) void dt_kernel(const float* __restrict__ dtw,
                                                  const float* __restrict__ dtb) {
    const int ROWS = 16;
    int m0 = blockIdx.x * ROWS;
    int n = threadIdx.x;
    __shared__ float s[ROWS][DTRANK];
    if (n < ROWS*DTRANK) {
        int r = n >> 5, k = n & 31;
        s[r][k] = g_dbc[(size_t)(m0+r)*64 + k];
    }
    __syncthreads();
    float w[32];
    #pragma unroll
    for (int k = 0; k < 32; k++) w[k] = dtw[k*DINNER + n];
    float bias = dtb[n];
    #pragma unroll 4
    for (int r = 0; r < ROWS; r++) {
        float acc = bias;
        #pragma unroll
        for (int k = 0; k < 32; k++) acc = fmaf(s[r][k], w[k], acc);
        float v = (acc > 20.f) ? acc : log1pf(__expf(acc));
        g_dt[(size_t)(m0+r)*DINNER + n] = v;
    }
}

// ---------------- selective scan + Dp skip + SiLU(z) gate ----------------
// one warp per 32 channels; prefetch depth 4; packed f32x2 math.
// FAST path exploits A_log = log(1..16)  =>  exp(dt*a_s) = exp(-dt)^(s+1).
template<bool FAST>
__device__ __forceinline__ void scan_body(size_t base, const float* __restrict__ bcp,
                                          const float (&a)[16], float Dv, int lane,
                                          float (*sBC)[32]) {
    float pdt[4], px[4], pz[4];
    #pragma unroll
    for (int i = 0; i < 4; i++) {
        size_t off = base + (size_t)i * DINNER;
        pdt[i] = g_dt[off]; px[i] = g_xc[off]; pz[i] = g_z[off];
        sBC[i][lane] = bcp[(size_t)i * 64];
    }
    __syncwarp();

    uint64_t h[8];
    #pragma unroll
    for (int i = 0; i < 8; i++) h[i] = 0ull;

    for (int t0 = 0; t0 < SEQ; t0 += 4) {
        int sb = t0 & 4;
        #pragma unroll
        for (int u = 0; u < 4; u++) {
            int t = t0 + u;
            float dtv = pdt[u], xv = px[u], zv = pz[u];
            int tn = t + 4;
            if (tn < SEQ) {
                size_t offn = base + (size_t)tn * DINNER;
                pdt[u] = g_dt[offn]; px[u] = g_xc[offn]; pz[u] = g_z[offn];
                sBC[(sb ^ 4) + u][lane] = bcp[(size_t)tn * 64];
            }
            float dtx = dtv * xv;
            uint64_t dtxp; PACK2(dtxp, dtx, dtx);
            uint64_t rp, e2p;
            if (FAST) {
                float e1 = __expf(-dtv);
                float e2 = e1 * e1;
                PACK2(rp, e1, e2);
                PACK2(e2p, e2, e2);
            }
            uint64_t yp = 0ull;
            const uint64_t* bc2 = reinterpret_cast<const uint64_t*>(sBC[sb + u]);
            #pragma unroll
            for (int k = 0; k < 8; k++) {
                uint64_t rk;
                if (FAST) {
                    rk = rp;
                    if (k < 7) FMUL2(rp, rp, e2p);
                } else {
                    float rl = __expf(dtv * a[2*k]);
                    float rh = __expf(dtv * a[2*k + 1]);
                    PACK2(rk, rl, rh);
                }
                uint64_t bx; FMUL2(bx, dtxp, bc2[k]);
                FFMA2(h[k], rk, h[k], bx);
                FFMA2(yp, h[k], bc2[8 + k], yp);
            }
            float ylo, yhi; UNPACK2(ylo, yhi, yp);
            float yv = ylo + yhi;
            float sg = __fdividef(zv, 1.f + __expf(-zv));   // silu(z)
            g_y[base + (size_t)t * DINNER] = fmaf(xv, Dv, yv) * sg;
        }
        __syncwarp();
    }
}

__global__ __launch_bounds__(32) void scan_kernel(const float* __restrict__ A_log,
                                                  const float* __restrict__ Dp) {
    __shared__ __align__(16) float sBC[8][32];
    int b = blockIdx.x;
    int lane = threadIdx.x;
    int d = blockIdx.y * 32 + lane;
    float a[16];
    bool fast = true;
    #pragma unroll
    for (int s = 0; s < 16; s++) {
        a[s] = -__expf(A_log[(size_t)d*DSTATE + s]);
        fast = fast && (fabsf(a[s] + (float)(s+1)) <= 1e-4f * (float)(s+1));
    }
    fast = __all_sync(FULLMASK, fast);
    float Dv = Dp[d];
    size_t base = (size_t)b * SEQ * DINNER + d;
    const float* bcp = g_dbc + (size_t)b * SEQ * 64 + 32 + lane;
    if (fast) scan_body<true >(base, bcp, a, Dv, lane, sBC);
    else      scan_body<false>(base, bcp, a, Dv, lane, sBC);
}

// ---------------- out-proj GEMM (double-buffered) + residual combine -------
// g_y[8192x1024] @ out_w[1024x512]; dir0: out = x + 0.5*acc; dir1: out += 0.5*acc
// at the time-flipped row.
__global__ __launch_bounds__(256) void gemm_out_kernel(const float* __restrict__ Bw,
                                                       const float* __restrict__ x,
                                                       float* __restrict__ out, int dir) {
    const int K = DINNER, N = DIM, KT = K/16;
    __shared__ float As[2][16][132];
    __shared__ float Bs[2][16][128];
    int bm = blockIdx.y * 128;
    int bn = blockIdx.x * 128;
    int tid = threadIdx.x;
    int tr = tid >> 4, tc = tid & 15;
    int arow0 = tid >> 2, ac4 = (tid & 3) << 2;

    float4 ra[2], rb[2];
    auto loadT = [&](int k0) {
        #pragma unroll
        for (int i = 0; i < 2; i++) {
            int row = arow0 + i*64;
            ra[i] = *(const float4*)(g_y + (size_t)(bm+row)*K + k0 + ac4);
        }
        #pragma unroll
        for (int i = 0; i < 2; i++) {
            int id = tid + i*256;
            int row = id >> 5, c4 = (id & 31) << 2;
            rb[i] = *(const float4*)(Bw + (size_t)(k0+row)*N + bn + c4);
        }
    };
    auto storeT = [&](int buf) {
        #pragma unroll
        for (int i = 0; i < 2; i++) {
            int row = arow0 + i*64;
            As[buf][ac4][row]   = ra[i].x; As[buf][ac4+1][row] = ra[i].y;
            As[buf][ac4+2][row] = ra[i].z; As[buf][ac4+3][row] = ra[i].w;
        }
        #pragma unroll
        for (int i = 0; i < 2; i++) {
            int id = tid + i*256;
            int row = id >> 5, c4 = (id & 31) << 2;
            *(float4*)&Bs[buf][row][c4] = rb[i];
        }
    };

    float acc[8][8] = {};
    loadT(0); storeT(0); __syncthreads();
    loadT(16);
    for (int kt = 0; kt < KT; kt++) {
        int cur = kt & 1;
        if (kt + 1 < KT) storeT(cur ^ 1);
        if (kt + 2 < KT) loadT((kt + 2) * 16);
        #pragma unroll
        for (int k = 0; k < 16; k++) {
            float av[8], bv[8];
            *(float4*)&av[0] = *(const float4*)&As[cur][k][tr*8];
            *(float4*)&av[4] = *(const float4*)&As[cur][k][tr*8 + 4];
            *(float4*)&bv[0] = *(const float4*)&Bs[cur][k][tc*8];
            *(float4*)&bv[4] = *(const float4*)&Bs[cur][k][tc*8 + 4];
            #pragma unroll
            for (int i = 0; i < 8; i++)
                #pragma unroll
                for (int j = 0; j < 8; j++) acc[i][j] = fmaf(av[i], bv[j], acc[i][j]);
        }
        __syncthreads();
    }
    #pragma unroll
    for (int i = 0; i < 8; i++) {
        int m = bm + tr*8 + i;
        int t = m & (SEQ-1);
        int grow = (m & ~(SEQ-1)) + (dir ? (SEQ-1 - t) : t);
        #pragma unroll
        for (int j = 0; j < 8; j += 4) {
            int n = bn + tc*8 + j;
            float4 v = {0.5f*acc[i][j], 0.5f*acc[i][j+1], 0.5f*acc[i][j+2], 0.5f*acc[i][j+3]};
            float* op = out + (size_t)grow*DIM + n;
            if (dir == 0) {
                float4 xv = *(const float4*)(x + (size_t)grow*DIM + n);
                v.x += xv.x; v.y += xv.y; v.z += xv.z; v.w += xv.w;
            } else {
                float4 ov = *(const float4*)op;
                v.x += ov.x; v.y += ov.y; v.z += ov.z; v.w += ov.w;
            }
            *(float4*)op = v;
        }
    }
}

// ---------------- launch ----------------
extern "C" void kernel_launch(void* const* d_in, const int* in_sizes, int n_in,
                              void* d_out, int out_size) {
    const float* x    = (const float*)d_in[0];
    const float* ln_g = (const float*)d_in[1];
    const float* ln_b = (const float*)d_in[2];

    ln_kernel<<<NTOK, 256>>>(x, ln_g, ln_b);

    for (int dir = 0; dir < 2; dir++) {
        const float* in_w    = (const float*)d_in[3 + 9*dir + 0];
        const float* conv_w  = (const float*)d_in[3 + 9*dir + 1];
        const float* conv_b  = (const float*)d_in[3 + 9*dir + 2];
        const float* xproj_w = (const float*)d_in[3 + 9*dir + 3];
        const float* dt_w    = (const float*)d_in[3 + 9*dir + 4];
        const float* dt_b    = (const float*)d_in[3 + 9*dir + 5];
        const float* A_log   = (const float*)d_in[3 + 9*dir + 6];
        const float* Dp      = (const float*)d_in[3 + 9*dir + 7];
        const float* out_w   = (const float*)d_in[3 + 9*dir + 8];

        gemm_in_kernel<<<dim3(2*DINNER/128, NTOK/128), 256>>>(in_w, dir);
        conv_kernel<<<(NTOK*(size_t)DINNER)/256, 256>>>(conv_w, conv_b);
        xproj_kernel<<<NTOK/64, 256>>>(xproj_w);
        dt_kernel<<<NTOK/16, 1024>>>(dt_w, dt_b);
        scan_kernel<<<dim3(BATCH, DINNER/32), 32>>>(A_log, Dp);
        gemm_out_kernel<<<dim3(DIM/128, NTOK/128), 256>>>(out_w, x, (float*)d_out, dir);
    }
}

// round 6
// speedup vs baseline: 1.6757x; 1.1423x over previous
#include <cuda_runtime.h>
#include <cuda_bf16.h>
#include <cstdint>

#define BATCH 4
#define SEQ 2048
#define DIM 512
#define DSTATE 16
#define DCONV 4
#define DINNER 1024
#define DTRANK 32
#define NTOK (BATCH*SEQ)   // 8192
#define FULLMASK 0xffffffffu

// ---------------- packed f32x2 helpers ----------------
#define PACK2(out, lo, hi) asm("mov.b64 %0, {%1, %2};" : "=l"(out) : "f"(lo), "f"(hi))
#define UNPACK2(lo, hi, v) asm("mov.b64 {%0, %1}, %2;" : "=f"(lo), "=f"(hi) : "l"(v))
#define FMUL2(d, a, b)     asm("mul.rn.f32x2 %0, %1, %2;" : "=l"(d) : "l"(a), "l"(b))
#define FFMA2(d, a, b, c)  asm("fma.rn.f32x2 %0, %1, %2, %3;" : "=l"(d) : "l"(a), "l"(b), "l"(c))

// ---------------- mma.sync / ldmatrix / cp.async helpers (sm_80+, no 'a' needed) ----
__device__ __forceinline__ uint32_t smem_u32(const void* p) {
    uint32_t a;
    asm("{ .reg .u64 t; cvta.to.shared.u64 t, %1; cvt.u32.u64 %0, t; }" : "=r"(a) : "l"(p));
    return a;
}
#define CP16(dst, src) asm volatile("cp.async.cg.shared.global [%0], [%1], 16;" :: "r"(dst), "l"(src))
#define CP_COMMIT()    asm volatile("cp.async.commit_group;" ::: "memory")
#define CP_WAIT1()     asm volatile("cp.async.wait_group 1;" ::: "memory")
#define LDSM4(r, addr) \
    asm volatile("ldmatrix.sync.aligned.m8n8.x4.shared.b16 {%0,%1,%2,%3}, [%4];" \
        : "=r"((r)[0]), "=r"((r)[1]), "=r"((r)[2]), "=r"((r)[3]) : "r"(addr))
#define MMA16816(c, a, b0, b1) \
    asm volatile("mma.sync.aligned.m16n8k16.row.col.f32.bf16.bf16.f32 " \
        "{%0,%1,%2,%3}, {%4,%5,%6,%7}, {%8,%9}, {%0,%1,%2,%3};" \
        : "+f"((c)[0]), "+f"((c)[1]), "+f"((c)[2]), "+f"((c)[3]) \
        : "r"((a)[0]), "r"((a)[1]), "r"((a)[2]), "r"((a)[3]), "r"(b0), "r"(b1))

// ---------------- scratch (device globals: allocation-free) ----------------
__device__ float g_xm [(size_t)NTOK*DINNER];
__device__ float g_z  [(size_t)NTOK*DINNER];
__device__ float g_xc [(size_t)NTOK*DINNER];
__device__ float g_dbc[(size_t)NTOK*64];
__device__ float g_dt [(size_t)NTOK*DINNER];
// bf16 hi/lo activations (GEMM A operands)
__device__ __nv_bfloat16 g_w_hi [(size_t)NTOK*DIM],    g_w_lo [(size_t)NTOK*DIM];
__device__ __nv_bfloat16 g_xc_hi[(size_t)NTOK*DINNER], g_xc_lo[(size_t)NTOK*DINNER];
__device__ __nv_bfloat16 g_y_hi [(size_t)NTOK*DINNER], g_y_lo [(size_t)NTOK*DINNER];
// transposed/split weights (bf16, K-major [N][K])
__device__ __nv_bfloat16 g_wt_in_hi[2048*512],  g_wt_in_lo[2048*512];
__device__ __nv_bfloat16 g_wt_out_hi[512*1024], g_wt_out_lo[512*1024];
__device__ __nv_bfloat16 g_wt_xp_hi[64*1024],   g_wt_xp_lo[64*1024];

__device__ __forceinline__ void split_store(__nv_bfloat16* hi, __nv_bfloat16* lo,
                                            size_t o, float v) {
    __nv_bfloat16 h = __float2bfloat16(v);
    hi[o] = h;
    lo[o] = __float2bfloat16(v - __bfloat162float(h));
}

// ---------------- weight transpose + hi/lo split ----------------
// W [K x N] row-major fp32  ->  Wt_hi/Wt_lo [N x K] bf16
__global__ void split_w_kernel(const float* __restrict__ W, int K, int N, int which) {
    __nv_bfloat16* hi = (which == 0) ? g_wt_in_hi : (which == 1) ? g_wt_out_hi : g_wt_xp_hi;
    __nv_bfloat16* lo = (which == 0) ? g_wt_in_lo : (which == 1) ? g_wt_out_lo : g_wt_xp_lo;
    __shared__ float t[32][33];
    int n0 = blockIdx.x * 32, k0 = blockIdx.y * 32;
    int tx = threadIdx.x, ty = threadIdx.y;  // 32 x 8
    #pragma unroll
    for (int i = 0; i < 32; i += 8)
        t[ty + i][tx] = W[(size_t)(k0 + ty + i) * N + n0 + tx];
    __syncthreads();
    #pragma unroll
    for (int i = 0; i < 32; i += 8)
        split_store(hi, lo, (size_t)(n0 + ty + i) * K + k0 + tx, t[tx][ty + i]);
}

// ---------------- tensor-core split-bf16 GEMM (mma.sync) ----------------
// C[8192 x N] = A x B, fp32-ish accuracy via 2-limb bf16 split (3 products).
// EPI: 0 = in-proj (A=w hi/lo, flip rows for dir1, write g_xm|g_z fp32)
//      1 = out-proj (A=y hi/lo, write out = {x|out} + 0.5*acc at flipped row)
//      2 = xproj  (A=xc hi/lo, write g_dbc fp32)
template<int BN, int EPI>
__global__ __launch_bounds__(256) void mma_gemm_kernel(const float* __restrict__ xres,
                                                       float* __restrict__ outp, int flip) {
    constexpr int BM = 128, BK = 32;
    constexpr int KF = (EPI == 0) ? DIM : DINNER;
    constexpr int NC = KF / BK;
    constexpr int ROWB = 80;                 // bytes/smem row: 32 bf16 data + 8 pad
    constexpr int AT = BM * ROWB;            // 10240 B per A limb tile
    constexpr int BT = BN * ROWB;
    constexpr int STAGE = 2 * AT + 2 * BT;
    constexpr int WN = BN / 2;               // warp tile N (warps: 4 along M, 2 along N)
    constexpr int NT = WN / 8;               // n8 tiles per warp

    extern __shared__ char smem[];
    uint32_t sb = smem_u32(smem);
    int tid = threadIdx.x, wid = tid >> 5, lane = tid & 31;
    int wm = wid & 3, wn = wid >> 2;
    int bm = blockIdx.y * BM, bn = blockIdx.x * BN;

    const __nv_bfloat16* Ahi = (EPI == 0) ? g_w_hi : (EPI == 1) ? g_y_hi : g_xc_hi;
    const __nv_bfloat16* Alo = (EPI == 0) ? g_w_lo : (EPI == 1) ? g_y_lo : g_xc_lo;
    const __nv_bfloat16* Bhi = (EPI == 0) ? g_wt_in_hi : (EPI == 1) ? g_wt_out_hi : g_wt_xp_hi;
    const __nv_bfloat16* Blo = (EPI == 0) ? g_wt_in_lo : (EPI == 1) ? g_wt_out_lo : g_wt_xp_lo;

    auto issue = [&](int chunk) {
        int k0 = chunk * BK;
        uint32_t sbase = sb + (chunk % 3) * STAGE;
        #pragma unroll
        for (int l = 0; l < 2; l++) {
            const __nv_bfloat16* src = l ? Alo : Ahi;
            #pragma unroll
            for (int e = 0; e < 2; e++) {
                int id = tid + e * 256;
                int row = id >> 2, q = id & 3;
                int grow = bm + row;
                if (EPI == 0 && flip) grow = (grow & ~(SEQ-1)) + (SEQ-1 - (grow & (SEQ-1)));
                CP16(sbase + l*AT + row*ROWB + q*16, src + (size_t)grow*KF + k0 + q*8);
            }
        }
        #pragma unroll
        for (int l = 0; l < 2; l++) {
            const __nv_bfloat16* src = l ? Blo : Bhi;
            #pragma unroll
            for (int e = 0; e < BN/64; e++) {
                int id = tid + e * 256;
                int row = id >> 2, q = id & 3;
                CP16(sbase + 2*AT + l*BT + row*ROWB + q*16,
                     src + (size_t)(bn + row)*KF + k0 + q*8);
            }
        }
    };

    float acc[2][NT][4];
    #pragma unroll
    for (int mt = 0; mt < 2; mt++)
        #pragma unroll
        for (int nt = 0; nt < NT; nt++)
            #pragma unroll
            for (int j = 0; j < 4; j++) acc[mt][nt][j] = 0.f;

    issue(0); CP_COMMIT();
    issue(1); CP_COMMIT();

    for (int i = 0; i < NC; i++) {
        CP_WAIT1();
        __syncthreads();
        if (i + 2 < NC) issue(i + 2);
        CP_COMMIT();

        uint32_t abase = sb + (i % 3) * STAGE;
        uint32_t bbase = abase + 2 * AT;
        #pragma unroll
        for (int ks = 0; ks < 2; ks++) {
            uint32_t a[2][2][4];
            #pragma unroll
            for (int l = 0; l < 2; l++)
                #pragma unroll
                for (int mt = 0; mt < 2; mt++) {
                    uint32_t ad = abase + l*AT + (wm*32 + mt*16 + (lane & 15))*ROWB
                                + ks*32 + (lane >> 4)*16;
                    LDSM4(a[l][mt], ad);
                }
            uint32_t b[2][NT/2][4];
            #pragma unroll
            for (int l = 0; l < 2; l++)
                #pragma unroll
                for (int p = 0; p < NT/2; p++) {
                    uint32_t bd = bbase + l*BT + (wn*WN + p*16 + (lane & 15))*ROWB
                                + ks*32 + (lane >> 4)*16;
                    LDSM4(b[l][p], bd);
                }
            // x4 reg order: r0=(rows0-7,k0-7) r1=(rows8-15,k0-7) r2=(rows0-7,k8-15) r3=(rows8-15,k8-15)
            #pragma unroll
            for (int mt = 0; mt < 2; mt++)
                #pragma unroll
                for (int nt = 0; nt < NT; nt++) {
                    int p = nt >> 1, o = nt & 1;
                    MMA16816(acc[mt][nt], a[0][mt], b[0][p][o], b[0][p][o + 2]); // Ah*Bh
                    MMA16816(acc[mt][nt], a[0][mt], b[1][p][o], b[1][p][o + 2]); // Ah*Bl
                    MMA16816(acc[mt][nt], a[1][mt], b[0][p][o], b[0][p][o + 2]); // Al*Bh
                }
        }
    }

    // epilogue: c frag: c0,c1=(row lane/4, col 2*(lane%4)+{0,1}); c2,c3 = row+8
    int r4 = lane >> 2, cc2 = (lane & 3) * 2;
    #pragma unroll
    for (int mt = 0; mt < 2; mt++)
        #pragma unroll
        for (int nt = 0; nt < NT; nt++) {
            int n = bn + wn*WN + nt*8 + cc2;
            #pragma unroll
            for (int hf = 0; hf < 2; hf++) {
                int m = bm + wm*32 + mt*16 + r4 + hf*8;
                float v0 = acc[mt][nt][hf*2], v1 = acc[mt][nt][hf*2 + 1];
                if (EPI == 0) {
                    float2 v = {v0, v1};
                    if (n < DINNER) *(float2*)&g_xm[(size_t)m*DINNER + n] = v;
                    else            *(float2*)&g_z [(size_t)m*DINNER + n - DINNER] = v;
                } else if (EPI == 2) {
                    float2 v = {v0, v1};
                    *(float2*)&g_dbc[(size_t)m*64 + n] = v;
                } else {
                    int t = m & (SEQ - 1);
                    int grow = (m & ~(SEQ - 1)) + (flip ? (SEQ - 1 - t) : t);
                    float* dst = outp + (size_t)grow*DIM + n;
                    const float* add = flip ? dst : (xres + (size_t)grow*DIM + n);
                    float2 av = *(const float2*)add;
                    float2 v = {fmaf(0.5f, v0, av.x), fmaf(0.5f, v1, av.y)};
                    *(float2*)dst = v;
                }
            }
        }
}

// ---------------- layernorm -> w hi/lo ----------------
__global__ void ln_kernel(const float* __restrict__ x, const float* __restrict__ g,
                          const float* __restrict__ b) {
    int row = blockIdx.x;
    const float* xr = x + (size_t)row * DIM;
    int tid = threadIdx.x;
    float v0 = xr[tid], v1 = xr[tid + 256];
    float s = v0 + v1, qq = v0*v0 + v1*v1;
    __shared__ float ss[8], sq[8];
    #pragma unroll
    for (int o = 16; o > 0; o >>= 1) {
        s += __shfl_down_sync(FULLMASK, s, o);
        qq += __shfl_down_sync(FULLMASK, qq, o);
    }
    if ((tid & 31) == 0) { ss[tid >> 5] = s; sq[tid >> 5] = qq; }
    __syncthreads();
    __shared__ float mean_s, rstd_s;
    if (tid == 0) {
        float st = 0.f, qt = 0.f;
        #pragma unroll
        for (int i = 0; i < 8; i++) { st += ss[i]; qt += sq[i]; }
        float m = st / DIM;
        mean_s = m;
        rstd_s = rsqrtf(qt / DIM - m*m + 1e-5f);
    }
    __syncthreads();
    float m = mean_s, r = rstd_s;
    float w0 = (v0 - m)*r*g[tid]       + b[tid];
    float w1 = (v1 - m)*r*g[tid + 256] + b[tid + 256];
    split_store(g_w_hi, g_w_lo, (size_t)row*DIM + tid,       w0);
    split_store(g_w_hi, g_w_lo, (size_t)row*DIM + tid + 256, w1);
}

// ---------------- causal depthwise conv (k=4) + SiLU -> xc fp32 + hi/lo -----
__global__ void conv_kernel(const float* __restrict__ cw, const float* __restrict__ cb) {
    size_t idx = (size_t)blockIdx.x * blockDim.x + threadIdx.x;
    int d = (int)(idx & (DINNER-1));
    int t = (int)((idx >> 10) & (SEQ-1));
    float acc = cb[d];
    #pragma unroll
    for (int k = 0; k < DCONV; k++) {
        int ts = t + k - (DCONV-1);
        if (ts >= 0)
            acc = fmaf(g_xm[idx + (size_t)((long)k - (DCONV-1)) * DINNER], cw[k*DINNER + d], acc);
    }
    float sg = 1.f / (1.f + __expf(-acc));
    float v = acc * sg;
    g_xc[idx] = v;
    split_store(g_xc_hi, g_xc_lo, idx, v);
}

// ---------------- dt GEMM (K=32) + bias + softplus ----------------
__global__ __launch_bounds__(1024) void dt_kernel(const float* __restrict__ dtw,
                                                  const float* __restrict__ dtb) {
    const int ROWS = 16;
    int m0 = blockIdx.x * ROWS;
    int n = threadIdx.x;
    __shared__ float s[ROWS][DTRANK];
    if (n < ROWS*DTRANK) {
        int r = n >> 5, k = n & 31;
        s[r][k] = g_dbc[(size_t)(m0+r)*64 + k];
    }
    __syncthreads();
    float w[32];
    #pragma unroll
    for (int k = 0; k < 32; k++) w[k] = dtw[k*DINNER + n];
    float bias = dtb[n];
    #pragma unroll 4
    for (int r = 0; r < ROWS; r++) {
        float acc = bias;
        #pragma unroll
        for (int k = 0; k < 32; k++) acc = fmaf(s[r][k], w[k], acc);
        float v = (acc > 20.f) ? acc : log1pf(__expf(acc));
        g_dt[(size_t)(m0+r)*DINNER + n] = v;
    }
}

// ---------------- selective scan + Dp skip + SiLU(z) gate -> y hi/lo -------
template<bool FAST>
__device__ __forceinline__ void scan_body(size_t base, const float* __restrict__ bcp,
                                          const float (&a)[16], float Dv, int lane,
                                          float (*sBC)[32]) {
    float pdt[4], px[4], pz[4];
    #pragma unroll
    for (int i = 0; i < 4; i++) {
        size_t off = base + (size_t)i * DINNER;
        pdt[i] = g_dt[off]; px[i] = g_xc[off]; pz[i] = g_z[off];
        sBC[i][lane] = bcp[(size_t)i * 64];
    }
    __syncwarp();
    uint64_t h[8];
    #pragma unroll
    for (int i = 0; i < 8; i++) h[i] = 0ull;

    for (int t0 = 0; t0 < SEQ; t0 += 4) {
        int sb = t0 & 4;
        #pragma unroll
        for (int u = 0; u < 4; u++) {
            int t = t0 + u;
            float dtv = pdt[u], xv = px[u], zv = pz[u];
            int tn = t + 4;
            if (tn < SEQ) {
                size_t offn = base + (size_t)tn * DINNER;
                pdt[u] = g_dt[offn]; px[u] = g_xc[offn]; pz[u] = g_z[offn];
                sBC[(sb ^ 4) + u][lane] = bcp[(size_t)tn * 64];
            }
            float dtx = dtv * xv;
            uint64_t dtxp; PACK2(dtxp, dtx, dtx);
            uint64_t rp, e2p;
            if (FAST) {
                float e1 = __expf(-dtv);
                float e2 = e1 * e1;
                PACK2(rp, e1, e2);
                PACK2(e2p, e2, e2);
            }
            uint64_t yp = 0ull;
            const uint64_t* bc2 = reinterpret_cast<const uint64_t*>(sBC[sb + u]);
            #pragma unroll
            for (int k = 0; k < 8; k++) {
                uint64_t rk;
                if (FAST) {
                    rk = rp;
                    if (k < 7) FMUL2(rp, rp, e2p);
                } else {
                    float rl = __expf(dtv * a[2*k]);
                    float rh = __expf(dtv * a[2*k + 1]);
                    PACK2(rk, rl, rh);
                }
                uint64_t bx; FMUL2(bx, dtxp, bc2[k]);
                FFMA2(h[k], rk, h[k], bx);
                FFMA2(yp, h[k], bc2[8 + k], yp);
            }
            float ylo, yhi; UNPACK2(ylo, yhi, yp);
            float yv = ylo + yhi;
            float sg = __fdividef(zv, 1.f + __expf(-zv));
            float yo = fmaf(xv, Dv, yv) * sg;
            split_store(g_y_hi, g_y_lo, base + (size_t)t * DINNER, yo);
        }
        __syncwarp();
    }
}

__global__ __launch_bounds__(32) void scan_kernel(const float* __restrict__ A_log,
                                                  const float* __restrict__ Dp) {
    __shared__ __align__(16) float sBC[8][32];
    int b = blockIdx.x;
    int lane = threadIdx.x;
    int d = blockIdx.y * 32 + lane;
    float a[16];
    bool fast = true;
    #pragma unroll
    for (int s = 0; s < 16; s++) {
        a[s] = -__expf(A_log[(size_t)d*DSTATE + s]);
        fast = fast && (fabsf(a[s] + (float)(s+1)) <= 1e-4f * (float)(s+1));
    }
    fast = __all_sync(FULLMASK, fast);
    float Dv = Dp[d];
    size_t base = (size_t)b * SEQ * DINNER + d;
    const float* bcp = g_dbc + (size_t)b * SEQ * 64 + 32 + lane;
    if (fast) scan_body<true >(base, bcp, a, Dv, lane, sBC);
    else      scan_body<false>(base, bcp, a, Dv, lane, sBC);
}

// ---------------- launch ----------------
#define SMEM_MMA_128 (3 * (2*10240 + 2*10240))   // 122880
#define SMEM_MMA_64  (3 * (2*10240 + 2*5120))    //  92160

extern "C" void kernel_launch(void* const* d_in, const int* in_sizes, int n_in,
                              void* d_out, int out_size) {
    const float* x    = (const float*)d_in[0];
    const float* ln_g = (const float*)d_in[1];
    const float* ln_b = (const float*)d_in[2];

    cudaFuncSetAttribute(mma_gemm_kernel<128,0>, cudaFuncAttributeMaxDynamicSharedMemorySize, SMEM_MMA_128);
    cudaFuncSetAttribute(mma_gemm_kernel<128,1>, cudaFuncAttributeMaxDynamicSharedMemorySize, SMEM_MMA_128);
    cudaFuncSetAttribute(mma_gemm_kernel<64,2>,  cudaFuncAttributeMaxDynamicSharedMemorySize, SMEM_MMA_64);

    ln_kernel<<<NTOK, 256>>>(x, ln_g, ln_b);

    for (int dir = 0; dir < 2; dir++) {
        const float* in_w    = (const float*)d_in[3 + 9*dir + 0];
        const float* conv_w  = (const float*)d_in[3 + 9*dir + 1];
        const float* conv_b  = (const float*)d_in[3 + 9*dir + 2];
        const float* xproj_w = (const float*)d_in[3 + 9*dir + 3];
        const float* dt_w    = (const float*)d_in[3 + 9*dir + 4];
        const float* dt_b    = (const float*)d_in[3 + 9*dir + 5];
        const float* A_log   = (const float*)d_in[3 + 9*dir + 6];
        const float* Dp      = (const float*)d_in[3 + 9*dir + 7];
        const float* out_w   = (const float*)d_in[3 + 9*dir + 8];

        split_w_kernel<<<dim3(2048/32, 512/32),  dim3(32,8)>>>(in_w,    512,  2048, 0);
        split_w_kernel<<<dim3(512/32,  1024/32), dim3(32,8)>>>(out_w,   1024, 512,  1);
        split_w_kernel<<<dim3(64/32,   1024/32), dim3(32,8)>>>(xproj_w, 1024, 64,   2);

        mma_gemm_kernel<128,0><<<dim3(2048/128, NTOK/128), 256, SMEM_MMA_128>>>(nullptr, nullptr, dir);
        conv_kernel<<<(NTOK*(size_t)DINNER)/256, 256>>>(conv_w, conv_b);
        mma_gemm_kernel<64,2><<<dim3(1, NTOK/128), 256, SMEM_MMA_64>>>(nullptr, nullptr, 0);
        dt_kernel<<<NTOK/16, 1024>>>(dt_w, dt_b);
        scan_kernel<<<dim3(BATCH, DINNER/32), 32>>>(A_log, Dp);
        mma_gemm_kernel<128,1><<<dim3(DIM/128, NTOK/128), 256, SMEM_MMA_128>>>(x, (float*)d_out, dir);
    }
}

// round 7
// speedup vs baseline: 1.7663x; 1.0541x over previous
#include <cuda_runtime.h>
#include <cuda_bf16.h>
#include <cstdint>

#define BATCH 4
#define SEQ 2048
#define DIM 512
#define DSTATE 16
#define DCONV 4
#define DINNER 1024
#define DTRANK 32
#define NTOK (BATCH*SEQ)   // 8192
#define FULLMASK 0xffffffffu

// ---------------- packed f32x2 helpers ----------------
#define PACK2(out, lo, hi) asm("mov.b64 %0, {%1, %2};" : "=l"(out) : "f"(lo), "f"(hi))
#define UNPACK2(lo, hi, v) asm("mov.b64 {%0, %1}, %2;" : "=f"(lo), "=f"(hi) : "l"(v))
#define FMUL2(d, a, b)     asm("mul.rn.f32x2 %0, %1, %2;" : "=l"(d) : "l"(a), "l"(b))
#define FFMA2(d, a, b, c)  asm("fma.rn.f32x2 %0, %1, %2, %3;" : "=l"(d) : "l"(a), "l"(b), "l"(c))

// ---------------- mma.sync / ldmatrix / cp.async helpers ----------------
__device__ __forceinline__ uint32_t smem_u32(const void* p) {
    uint32_t a;
    asm("{ .reg .u64 t; cvta.to.shared.u64 t, %1; cvt.u32.u64 %0, t; }" : "=r"(a) : "l"(p));
    return a;
}
#define CP16(dst, src) asm volatile("cp.async.cg.shared.global [%0], [%1], 16;" :: "r"(dst), "l"(src))
#define CP_COMMIT()    asm volatile("cp.async.commit_group;" ::: "memory")
#define CP_WAIT1()     asm volatile("cp.async.wait_group 1;" ::: "memory")
#define LDSM4(r, addr) \
    asm volatile("ldmatrix.sync.aligned.m8n8.x4.shared.b16 {%0,%1,%2,%3}, [%4];" \
        : "=r"((r)[0]), "=r"((r)[1]), "=r"((r)[2]), "=r"((r)[3]) : "r"(addr))
#define MMA16816(c, a, b0, b1) \
    asm volatile("mma.sync.aligned.m16n8k16.row.col.f32.bf16.bf16.f32 " \
        "{%0,%1,%2,%3}, {%4,%5,%6,%7}, {%8,%9}, {%0,%1,%2,%3};" \
        : "+f"((c)[0]), "+f"((c)[1]), "+f"((c)[2]), "+f"((c)[3]) \
        : "r"((a)[0]), "r"((a)[1]), "r"((a)[2]), "r"((a)[3]), "r"(b0), "r"(b1))

// ---------------- scratch (device globals: allocation-free) ----------------
__device__ float g_xm [(size_t)NTOK*DINNER];
__device__ float g_z  [(size_t)NTOK*DINNER];
__device__ float g_xc [(size_t)NTOK*DINNER];
__device__ float g_dbc[(size_t)NTOK*64];
__device__ float g_dt [(size_t)NTOK*DINNER];
// packed hi|lo bf16: [row][k/32][32 hi | 32 lo]  (one 128B line per row-chunk)
__device__ __align__(128) __nv_bfloat16 g_w2 [(size_t)NTOK*DIM*2];
__device__ __align__(128) __nv_bfloat16 g_xc2[(size_t)NTOK*DINNER*2];
__device__ __align__(128) __nv_bfloat16 g_y2 [(size_t)NTOK*DINNER*2];
__device__ __align__(128) __nv_bfloat16 g_wt_in [2048*512*2];
__device__ __align__(128) __nv_bfloat16 g_wt_out[512*1024*2];
__device__ __align__(128) __nv_bfloat16 g_wt_xp [64*1024*2];

__device__ __forceinline__ void split_store_pk(__nv_bfloat16* base, size_t row, int K2,
                                               int k, float v) {
    size_t o = row * (size_t)K2 + (size_t)((k >> 5) << 6) + (k & 31);
    __nv_bfloat16 h = __float2bfloat16(v);
    base[o] = h;
    base[o + 32] = __float2bfloat16(v - __bfloat162float(h));
}

// ---------------- weight transpose + hi/lo split (packed) ----------------
__global__ void split_w_kernel(const float* __restrict__ W, int K, int N, int which) {
    __nv_bfloat16* dst = (which == 0) ? g_wt_in : (which == 1) ? g_wt_out : g_wt_xp;
    __shared__ float t[32][33];
    int n0 = blockIdx.x * 32, k0 = blockIdx.y * 32;
    int tx = threadIdx.x, ty = threadIdx.y;  // 32 x 8
    #pragma unroll
    for (int i = 0; i < 32; i += 8)
        t[ty + i][tx] = W[(size_t)(k0 + ty + i) * N + n0 + tx];
    __syncthreads();
    #pragma unroll
    for (int i = 0; i < 32; i += 8)
        split_store_pk(dst, (size_t)(n0 + ty + i), 2*K, k0 + tx, t[tx][ty + i]);
}

__global__ void pad_kernel() {}

// ---------------- tensor-core split-bf16 GEMM (mma.sync, packed feed) -------
// EPI: 0 = in-proj (A=g_w2, flip rows for dir1, write g_xm|g_z fp32)
//      1 = out-proj (A=g_y2, write out = {x|out} + 0.5*acc at flipped row)
//      2 = xproj  (A=g_xc2, write g_dbc fp32)
template<int BN, int EPI>
__global__ __launch_bounds__(256, 2) void mma_gemm_kernel(const float* __restrict__ xres,
                                                          float* __restrict__ outp, int flip) {
    constexpr int BM = 128, BK = 32;
    constexpr int KF = (EPI == 0) ? DIM : DINNER;
    constexpr int NC = KF / BK;
    constexpr int AT = BM * 64;              // 8192 B per A limb tile (64B rows, swizzled)
    constexpr int BT = BN * 64;
    constexpr int STAGE = 2 * AT + 2 * BT;
    constexpr int WN = BN / 2;               // warps: 4 along M, 2 along N
    constexpr int NT = WN / 8;

    extern __shared__ char smem[];
    uint32_t sb = smem_u32(smem);
    int tid = threadIdx.x, wid = tid >> 5, lane = tid & 31;
    int wm = wid & 3, wn = wid >> 2;
    int bm = blockIdx.y * BM, bn = blockIdx.x * BN;

    const __nv_bfloat16* Apk = (EPI == 0) ? g_w2 : (EPI == 1) ? g_y2 : g_xc2;
    const __nv_bfloat16* Bpk = (EPI == 0) ? g_wt_in : (EPI == 1) ? g_wt_out : g_wt_xp;

    int r0 = tid >> 3, q = tid & 7;          // 8 threads cover one 128B row-chunk
    uint32_t halfA = (q >= 4) ? (uint32_t)AT : 0u;
    uint32_t halfB = (q >= 4) ? (uint32_t)BT : 0u;
    uint32_t dq = (uint32_t)(q & 3) << 4;

    auto issue = [&](int chunk) {
        uint32_t sbase = sb + (chunk % 3) * STAGE;
        #pragma unroll
        for (int e = 0; e < 4; e++) {
            int row = r0 + e * 32;
            int grow = bm + row;
            if (EPI == 0 && flip) grow = (grow & ~(SEQ-1)) + (SEQ-1 - (grow & (SEQ-1)));
            const char* src = (const char*)Apk + (size_t)grow * (4*KF) + chunk*128 + q*16;
            uint32_t dst = sbase + halfA + row*64 + (dq ^ ((uint32_t)((row >> 1) & 3) << 4));
            CP16(dst, src);
        }
        #pragma unroll
        for (int e = 0; e < BN/32; e++) {
            int row = r0 + e * 32;
            const char* src = (const char*)Bpk + (size_t)(bn + row) * (4*KF) + chunk*128 + q*16;
            uint32_t dst = sbase + 2*AT + halfB + row*64 + (dq ^ ((uint32_t)((row >> 1) & 3) << 4));
            CP16(dst, src);
        }
    };

    float acc[2][NT][4];
    #pragma unroll
    for (int mt = 0; mt < 2; mt++)
        #pragma unroll
        for (int nt = 0; nt < NT; nt++)
            #pragma unroll
            for (int j = 0; j < 4; j++) acc[mt][nt][j] = 0.f;

    issue(0); CP_COMMIT();
    issue(1); CP_COMMIT();

    for (int i = 0; i < NC; i++) {
        CP_WAIT1();
        __syncthreads();
        if (i + 2 < NC) issue(i + 2);
        CP_COMMIT();

        uint32_t abase = sb + (i % 3) * STAGE;
        uint32_t bbase = abase + 2 * AT;
        #pragma unroll
        for (int ks = 0; ks < 2; ks++) {
            uint32_t a[2][2][4];
            #pragma unroll
            for (int l = 0; l < 2; l++)
                #pragma unroll
                for (int mt = 0; mt < 2; mt++) {
                    int ar = wm*32 + mt*16 + (lane & 15);
                    uint32_t ch = (uint32_t)(ks*2 + (lane >> 4));
                    uint32_t ad = abase + l*AT + ar*64 + ((ch ^ (uint32_t)((ar >> 1) & 3)) << 4);
                    LDSM4(a[l][mt], ad);
                }
            uint32_t b[2][NT/2][4];
            #pragma unroll
            for (int l = 0; l < 2; l++)
                #pragma unroll
                for (int p = 0; p < NT/2; p++) {
                    int br = wn*WN + p*16 + (lane & 15);
                    uint32_t ch = (uint32_t)(ks*2 + (lane >> 4));
                    uint32_t bd = bbase + l*BT + br*64 + ((ch ^ (uint32_t)((br >> 1) & 3)) << 4);
                    LDSM4(b[l][p], bd);
                }
            #pragma unroll
            for (int mt = 0; mt < 2; mt++)
                #pragma unroll
                for (int nt = 0; nt < NT; nt++) {
                    int p = nt >> 1, o = nt & 1;
                    MMA16816(acc[mt][nt], a[0][mt], b[0][p][o], b[0][p][o + 2]); // Ah*Bh
                    MMA16816(acc[mt][nt], a[0][mt], b[1][p][o], b[1][p][o + 2]); // Ah*Bl
                    MMA16816(acc[mt][nt], a[1][mt], b[0][p][o], b[0][p][o + 2]); // Al*Bh
                }
        }
    }

    int r4 = lane >> 2, cc2 = (lane & 3) * 2;
    #pragma unroll
    for (int mt = 0; mt < 2; mt++)
        #pragma unroll
        for (int nt = 0; nt < NT; nt++) {
            int n = bn + wn*WN + nt*8 + cc2;
            #pragma unroll
            for (int hf = 0; hf < 2; hf++) {
                int m = bm + wm*32 + mt*16 + r4 + hf*8;
                float v0 = acc[mt][nt][hf*2], v1 = acc[mt][nt][hf*2 + 1];
                if (EPI == 0) {
                    float2 v = {v0, v1};
                    if (n < DINNER) *(float2*)&g_xm[(size_t)m*DINNER + n] = v;
                    else            *(float2*)&g_z [(size_t)m*DINNER + n - DINNER] = v;
                } else if (EPI == 2) {
                    float2 v = {v0, v1};
                    *(float2*)&g_dbc[(size_t)m*64 + n] = v;
                } else {
                    int t = m & (SEQ - 1);
                    int grow = (m & ~(SEQ - 1)) + (flip ? (SEQ - 1 - t) : t);
                    float* dst = outp + (size_t)grow*DIM + n;
                    const float* add = flip ? dst : (xres + (size_t)grow*DIM + n);
                    float2 av = *(const float2*)add;
                    float2 v = {fmaf(0.5f, v0, av.x), fmaf(0.5f, v1, av.y)};
                    *(float2*)dst = v;
                }
            }
        }
}

// ---------------- layernorm -> w packed hi/lo ----------------
__global__ void ln_kernel(const float* __restrict__ x, const float* __restrict__ g,
                          const float* __restrict__ b) {
    int row = blockIdx.x;
    const float* xr = x + (size_t)row * DIM;
    int tid = threadIdx.x;
    float v0 = xr[tid], v1 = xr[tid + 256];
    float s = v0 + v1, qq = v0*v0 + v1*v1;
    __shared__ float ss[8], sq[8];
    #pragma unroll
    for (int o = 16; o > 0; o >>= 1) {
        s += __shfl_down_sync(FULLMASK, s, o);
        qq += __shfl_down_sync(FULLMASK, qq, o);
    }
    if ((tid & 31) == 0) { ss[tid >> 5] = s; sq[tid >> 5] = qq; }
    __syncthreads();
    __shared__ float mean_s, rstd_s;
    if (tid == 0) {
        float st = 0.f, qt = 0.f;
        #pragma unroll
        for (int i = 0; i < 8; i++) { st += ss[i]; qt += sq[i]; }
        float m = st / DIM;
        mean_s = m;
        rstd_s = rsqrtf(qt / DIM - m*m + 1e-5f);
    }
    __syncthreads();
    float m = mean_s, r = rstd_s;
    split_store_pk(g_w2, row, 2*DIM, tid,       (v0 - m)*r*g[tid]       + b[tid]);
    split_store_pk(g_w2, row, 2*DIM, tid + 256, (v1 - m)*r*g[tid + 256] + b[tid + 256]);
}

// ---------------- causal depthwise conv (k=4) + SiLU ----------------
__global__ void conv_kernel(const float* __restrict__ cw, const float* __restrict__ cb) {
    size_t idx = (size_t)blockIdx.x * blockDim.x + threadIdx.x;
    int d = (int)(idx & (DINNER-1));
    int t = (int)((idx >> 10) & (SEQ-1));
    size_t row = idx >> 10;
    float acc = cb[d];
    #pragma unroll
    for (int k = 0; k < DCONV; k++) {
        int ts = t + k - (DCONV-1);
        if (ts >= 0)
            acc = fmaf(g_xm[idx + (size_t)((long)k - (DCONV-1)) * DINNER], cw[k*DINNER + d], acc);
    }
    float sg = 1.f / (1.f + __expf(-acc));
    float v = acc * sg;
    g_xc[idx] = v;
    split_store_pk(g_xc2, row, 2*DINNER, d, v);
}

// ---------------- dt GEMM (K=32) + bias + softplus ----------------
__global__ __launch_bounds__(1024) void dt_kernel(const float* __restrict__ dtw,
                                                  const float* __restrict__ dtb) {
    const int ROWS = 16;
    int m0 = blockIdx.x * ROWS;
    int n = threadIdx.x;
    __shared__ float s[ROWS][DTRANK];
    if (n < ROWS*DTRANK) {
        int r = n >> 5, k = n & 31;
        s[r][k] = g_dbc[(size_t)(m0+r)*64 + k];
    }
    __syncthreads();
    float w[32];
    #pragma unroll
    for (int k = 0; k < 32; k++) w[k] = dtw[k*DINNER + n];
    float bias = dtb[n];
    #pragma unroll 4
    for (int r = 0; r < ROWS; r++) {
        float acc = bias;
        #pragma unroll
        for (int k = 0; k < 32; k++) acc = fmaf(s[r][k], w[k], acc);
        float v = (acc > 20.f) ? acc : log1pf(__expf(acc));
        g_dt[(size_t)(m0+r)*DINNER + n] = v;
    }
}

// ---------------- selective scan + Dp skip + SiLU(z) gate -> y packed -------
template<bool FAST>
__device__ __forceinline__ void scan_body(size_t base, size_t rowbase, int d,
                                          const float* __restrict__ bcp,
                                          const float (&a)[16], float Dv, int lane,
                                          float (*sBC)[32]) {
    float pdt[4], px[4], pz[4];
    #pragma unroll
    for (int i = 0; i < 4; i++) {
        size_t off = base + (size_t)i * DINNER;
        pdt[i] = g_dt[off]; px[i] = g_xc[off]; pz[i] = g_z[off];
        sBC[i][lane] = bcp[(size_t)i * 64];
    }
    __syncwarp();
    uint64_t h[8];
    #pragma unroll
    for (int i = 0; i < 8; i++) h[i] = 0ull;

    for (int t0 = 0; t0 < SEQ; t0 += 4) {
        int sb = t0 & 4;
        #pragma unroll
        for (int u = 0; u < 4; u++) {
            int t = t0 + u;
            float dtv = pdt[u], xv = px[u], zv = pz[u];
            int tn = t + 4;
            if (tn < SEQ) {
                size_t offn = base + (size_t)tn * DINNER;
                pdt[u] = g_dt[offn]; px[u] = g_xc[offn]; pz[u] = g_z[offn];
                sBC[(sb ^ 4) + u][lane] = bcp[(size_t)tn * 64];
            }
            float dtx = dtv * xv;
            uint64_t dtxp; PACK2(dtxp, dtx, dtx);
            uint64_t rp, e2p;
            if (FAST) {
                float e1 = __expf(-dtv);
                float e2 = e1 * e1;
                PACK2(rp, e1, e2);
                PACK2(e2p, e2, e2);
            }
            uint64_t yp = 0ull;
            const uint64_t* bc2 = reinterpret_cast<const uint64_t*>(sBC[sb + u]);
            #pragma unroll
            for (int k = 0; k < 8; k++) {
                uint64_t rk;
                if (FAST) {
                    rk = rp;
                    if (k < 7) FMUL2(rp, rp, e2p);
                } else {
                    float rl = __expf(dtv * a[2*k]);
                    float rh = __expf(dtv * a[2*k + 1]);
                    PACK2(rk, rl, rh);
                }
                uint64_t bx; FMUL2(bx, dtxp, bc2[k]);
                FFMA2(h[k], rk, h[k], bx);
                FFMA2(yp, h[k], bc2[8 + k], yp);
            }
            float ylo, yhi; UNPACK2(ylo, yhi, yp);
            float yv = ylo + yhi;
            float sg = __fdividef(zv, 1.f + __expf(-zv));
            float yo = fmaf(xv, Dv, yv) * sg;
            split_store_pk(g_y2, rowbase + t, 2*DINNER, d, yo);
        }
        __syncwarp();
    }
}

__global__ __launch_bounds__(32) void scan_kernel(const float* __restrict__ A_log,
                                                  const float* __restrict__ Dp) {
    __shared__ __align__(16) float sBC[8][32];
    int b = blockIdx.x;
    int lane = threadIdx.x;
    int d = blockIdx.y * 32 + lane;
    float a[16];
    bool fast = true;
    #pragma unroll
    for (int s = 0; s < 16; s++) {
        a[s] = -__expf(A_log[(size_t)d*DSTATE + s]);
        fast = fast && (fabsf(a[s] + (float)(s+1)) <= 1e-4f * (float)(s+1));
    }
    fast = __all_sync(FULLMASK, fast);
    float Dv = Dp[d];
    size_t rowbase = (size_t)b * SEQ;
    size_t base = rowbase * DINNER + d;
    const float* bcp = g_dbc + (size_t)b * SEQ * 64 + 32 + lane;
    if (fast) scan_body<true >(base, rowbase, d, bcp, a, Dv, lane, sBC);
    else      scan_body<false>(base, rowbase, d, bcp, a, Dv, lane, sBC);
}

// ---------------- launch ----------------
#define SMEM_MMA_128 (3 * (2*8192 + 2*8192))   // 98304
#define SMEM_MMA_64  (3 * (2*8192 + 2*4096))   // 73728

extern "C" void kernel_launch(void* const* d_in, const int* in_sizes, int n_in,
                              void* d_out, int out_size) {
    const float* x    = (const float*)d_in[0];
    const float* ln_g = (const float*)d_in[1];
    const float* ln_b = (const float*)d_in[2];

    cudaFuncSetAttribute(mma_gemm_kernel<128,0>, cudaFuncAttributeMaxDynamicSharedMemorySize, SMEM_MMA_128);
    cudaFuncSetAttribute(mma_gemm_kernel<128,1>, cudaFuncAttributeMaxDynamicSharedMemorySize, SMEM_MMA_128);
    cudaFuncSetAttribute(mma_gemm_kernel<64,2>,  cudaFuncAttributeMaxDynamicSharedMemorySize, SMEM_MMA_64);

    ln_kernel<<<NTOK, 256>>>(x, ln_g, ln_b);   // launch 0

    for (int dir = 0; dir < 2; dir++) {
        const float* in_w    = (const float*)d_in[3 + 9*dir + 0];
        const float* conv_w  = (const float*)d_in[3 + 9*dir + 1];
        const float* conv_b  = (const float*)d_in[3 + 9*dir + 2];
        const float* xproj_w = (const float*)d_in[3 + 9*dir + 3];
        const float* dt_w    = (const float*)d_in[3 + 9*dir + 4];
        const float* dt_b    = (const float*)d_in[3 + 9*dir + 5];
        const float* A_log   = (const float*)d_in[3 + 9*dir + 6];
        const float* Dp      = (const float*)d_in[3 + 9*dir + 7];
        const float* out_w   = (const float*)d_in[3 + 9*dir + 8];

        split_w_kernel<<<dim3(2048/32, 512/32),  dim3(32,8)>>>(in_w,    512,  2048, 0); // 1
        split_w_kernel<<<dim3(512/32,  1024/32), dim3(32,8)>>>(out_w,   1024, 512,  1); // 2
        split_w_kernel<<<dim3(64/32,   1024/32), dim3(32,8)>>>(xproj_w, 1024, 64,   2); // 3
        if (dir == 0) pad_kernel<<<1, 32>>>();                                          // 4

        // launch 5 on dir 0 -> profiled by ncu (-s 5 -c 1)
        mma_gemm_kernel<128,0><<<dim3(2048/128, NTOK/128), 256, SMEM_MMA_128>>>(nullptr, nullptr, dir);
        conv_kernel<<<(NTOK*(size_t)DINNER)/256, 256>>>(conv_w, conv_b);
        mma_gemm_kernel<64,2><<<dim3(1, NTOK/128), 256, SMEM_MMA_64>>>(nullptr, nullptr, 0);
        dt_kernel<<<NTOK/16, 1024>>>(dt_w, dt_b);
        scan_kernel<<<dim3(BATCH, DINNER/32), 32>>>(A_log, Dp);
        mma_gemm_kernel<128,1><<<dim3(DIM/128, NTOK/128), 256, SMEM_MMA_128>>>(x, (float*)d_out, dir);
    }
}

// round 8
// speedup vs baseline: 1.8235x; 1.0324x over previous
#include <cuda_runtime.h>
#include <cuda_bf16.h>
#include <cstdint>

#define BATCH 4
#define SEQ 2048
#define DIM 512
#define DSTATE 16
#define DCONV 4
#define DINNER 1024
#define DTRANK 32
#define NTOK (BATCH*SEQ)   // 8192
#define FULLMASK 0xffffffffu

// ---------------- packed f32x2 helpers ----------------
#define PACK2(out, lo, hi) asm("mov.b64 %0, {%1, %2};" : "=l"(out) : "f"(lo), "f"(hi))
#define UNPACK2(lo, hi, v) asm("mov.b64 {%0, %1}, %2;" : "=f"(lo), "=f"(hi) : "l"(v))
#define FMUL2(d, a, b)     asm("mul.rn.f32x2 %0, %1, %2;" : "=l"(d) : "l"(a), "l"(b))
#define FFMA2(d, a, b, c)  asm("fma.rn.f32x2 %0, %1, %2, %3;" : "=l"(d) : "l"(a), "l"(b), "l"(c))

// ---------------- mma.sync / ldmatrix / bulk-async helpers ----------------
__device__ __forceinline__ uint32_t smem_u32(const void* p) {
    uint32_t a;
    asm("{ .reg .u64 t; cvta.to.shared.u64 t, %1; cvt.u32.u64 %0, t; }" : "=r"(a) : "l"(p));
    return a;
}
#define LDSM4(r, addr) \
    asm volatile("ldmatrix.sync.aligned.m8n8.x4.shared.b16 {%0,%1,%2,%3}, [%4];" \
        : "=r"((r)[0]), "=r"((r)[1]), "=r"((r)[2]), "=r"((r)[3]) : "r"(addr))
#define MMA16816(c, a, b0, b1) \
    asm volatile("mma.sync.aligned.m16n8k16.row.col.f32.bf16.bf16.f32 " \
        "{%0,%1,%2,%3}, {%4,%5,%6,%7}, {%8,%9}, {%0,%1,%2,%3};" \
        : "+f"((c)[0]), "+f"((c)[1]), "+f"((c)[2]), "+f"((c)[3]) \
        : "r"((a)[0]), "r"((a)[1]), "r"((a)[2]), "r"((a)[3]), "r"(b0), "r"(b1))
#define MBAR_INIT(a, c) asm volatile("mbarrier.init.shared.b64 [%0], %1;" :: "r"(a), "r"(c) : "memory")
#define MBAR_EXPECT_TX(a, n) asm volatile("mbarrier.arrive.expect_tx.shared.b64 _, [%0], %1;" :: "r"(a), "r"(n) : "memory")
#define MBAR_WAIT(a, p) do { \
    uint32_t _m = (a), _p = (p), _d; \
    asm volatile("{\n\t.reg .pred q;\n\tmbarrier.try_wait.parity.acquire.cta.shared::cta.b64 q, [%1], %2;\n\tselp.b32 %0, 1, 0, q;\n\t}" \
        : "=r"(_d) : "r"(_m), "r"(_p) : "memory"); \
    if (!_d) { asm volatile("{\n\t.reg .pred Q;\n\tWL%=:\n\tmbarrier.try_wait.parity.acquire.cta.shared::cta.b64 Q, [%0], %1, 0x989680;\n\t@Q bra.uni WD%=;\n\tbra.uni WL%=;\n\tWD%=:\n\t}" :: "r"(_m), "r"(_p) : "memory"); } \
} while (0)
#define BULKCP(dst, src, bytes, mbar) \
    asm volatile("cp.async.bulk.shared::cluster.global.mbarrier::complete_tx::bytes [%0], [%1], %2, [%3];" \
        :: "r"(dst), "l"(src), "r"(bytes), "r"(mbar) : "memory")

// ---------------- scratch (device globals: allocation-free) ----------------
__device__ float g_xm [(size_t)NTOK*DINNER];
__device__ float g_z  [(size_t)NTOK*DINNER];
__device__ float g_xc [(size_t)NTOK*DINNER];
__device__ float g_dbc[(size_t)NTOK*64];
__device__ float g_dt [(size_t)NTOK*DINNER];
// GEMM operands: [k-chunk][row][128B] where the 128B line = 8 x 16B units,
// unit u = limb*4 + (k8 sub-column), physically placed at (u ^ (row&7))*16.
// hi limb: u 0..3, lo limb: u 4..7. Pre-swizzled so a LINEAR bulk copy into
// smem yields a conflict-free ldmatrix layout.
__device__ __align__(128) __nv_bfloat16 g_w2 [(size_t)NTOK*DIM*2];
__device__ __align__(128) __nv_bfloat16 g_xc2[(size_t)NTOK*DINNER*2];
__device__ __align__(128) __nv_bfloat16 g_y2 [(size_t)NTOK*DINNER*2];
__device__ __align__(128) __nv_bfloat16 g_wt_in [2048*512*2];
__device__ __align__(128) __nv_bfloat16 g_wt_out[512*1024*2];
__device__ __align__(128) __nv_bfloat16 g_wt_xp [64*1024*2];

__device__ __forceinline__ void split_store_pk(void* basep, size_t nrows, size_t row,
                                               int k, float v) {
    char* p = (char*)basep + ((size_t)(k >> 5) * nrows + row) * 128;
    int c = (k >> 3) & 3, r7 = (int)(row & 7), bi = (k & 7) * 2;
    __nv_bfloat16 h = __float2bfloat16(v);
    *(__nv_bfloat16*)(p + (((c    ) ^ r7) << 4) + bi) = h;
    *(__nv_bfloat16*)(p + (((c + 4) ^ r7) << 4) + bi) = __float2bfloat16(v - __bfloat162float(h));
}

// ---------------- weight transpose + hi/lo split (chunk-major, pre-swizzled) ---
__global__ void split_w_kernel(const float* __restrict__ W, int K, int N, int which) {
    __nv_bfloat16* dst = (which == 0) ? g_wt_in : (which == 1) ? g_wt_out : g_wt_xp;
    __shared__ float t[32][33];
    int n0 = blockIdx.x * 32, k0 = blockIdx.y * 32;
    int tx = threadIdx.x, ty = threadIdx.y;  // 32 x 8
    #pragma unroll
    for (int i = 0; i < 32; i += 8)
        t[ty + i][tx] = W[(size_t)(k0 + ty + i) * N + n0 + tx];
    __syncthreads();
    #pragma unroll
    for (int i = 0; i < 32; i += 8)
        split_store_pk(dst, (size_t)N, (size_t)(n0 + ty + i), k0 + tx, t[tx][ty + i]);
}

__global__ void pad_kernel() {}

// ---------------- tensor-core split-bf16 GEMM (mma.sync + bulk-async feed) ----
// EPI: 0 = in-proj (A=g_w2, scatter rows on flip, write g_xm|g_z fp32)
//      1 = out-proj (A=g_y2, write out = {x|out} + 0.5*acc at flipped row)
//      2 = xproj  (A=g_xc2, write g_dbc fp32)
template<int BN, int EPI>
__global__ __launch_bounds__(256, 2) void mma_gemm_kernel(const float* __restrict__ xres,
                                                          float* __restrict__ outp, int flip) {
    constexpr int BM = 128;
    constexpr int KF = (EPI == 0) ? DIM : DINNER;
    constexpr int NB = (EPI == 0) ? 2048 : (EPI == 1) ? 512 : 64;
    constexpr int NC = KF / 32;
    constexpr int AT = BM * 128;             // 16384 B (both limbs)
    constexpr int BT = BN * 128;
    constexpr int STAGE = AT + BT;
    constexpr int WN = BN / 2;               // warps: 4 along M, 2 along N
    constexpr int NT = WN / 8;

    extern __shared__ char smem[];
    uint32_t sb = smem_u32(smem);
    int tid = threadIdx.x, wid = tid >> 5, lane = tid & 31;
    int wm = wid & 3, wn = wid >> 2;
    int bm = blockIdx.y * BM, bn = blockIdx.x * BN;

    const char* Apk = (const char*)((EPI == 0) ? g_w2 : (EPI == 1) ? g_y2 : g_xc2);
    const char* Bpk = (const char*)((EPI == 0) ? g_wt_in : (EPI == 1) ? g_wt_out : g_wt_xp);

    if (tid == 0) {
        MBAR_INIT(sb + 0, 1); MBAR_INIT(sb + 8, 1); MBAR_INIT(sb + 16, 1);
    }
    __syncthreads();

    auto issue = [&](int c) {        // tid 0 only
        int s = c % 3;
        uint32_t mb = sb + s * 8;
        uint32_t dst = sb + 128 + s * STAGE;
        MBAR_EXPECT_TX(mb, (uint32_t)STAGE);
        BULKCP(dst,      Apk + ((size_t)c * NTOK + bm) * 128, (uint32_t)AT, mb);
        BULKCP(dst + AT, Bpk + ((size_t)c * NB   + bn) * 128, (uint32_t)BT, mb);
    };
    if (tid == 0) { issue(0); issue(1); issue(2); }

    float acc[2][NT][4];
    #pragma unroll
    for (int mt = 0; mt < 2; mt++)
        #pragma unroll
        for (int nt = 0; nt < NT; nt++)
            #pragma unroll
            for (int j = 0; j < 4; j++) acc[mt][nt][j] = 0.f;

    for (int i = 0; i < NC; i++) {
        MBAR_WAIT(sb + (i % 3) * 8, (i / 3) & 1);
        uint32_t abase = sb + 128 + (i % 3) * STAGE;
        uint32_t bbase = abase + AT;
        #pragma unroll
        for (int ks = 0; ks < 2; ks++) {
            int cc = ks * 2 + (lane >> 4);
            uint32_t a[2][2][4];
            #pragma unroll
            for (int l = 0; l < 2; l++)
                #pragma unroll
                for (int mt = 0; mt < 2; mt++) {
                    int ar = wm*32 + mt*16 + (lane & 15);
                    uint32_t ad = abase + ar*128 + (uint32_t)(((l*4 + cc) ^ (ar & 7)) << 4);
                    LDSM4(a[l][mt], ad);
                }
            uint32_t b[2][NT/2][4];
            #pragma unroll
            for (int l = 0; l < 2; l++)
                #pragma unroll
                for (int p = 0; p < NT/2; p++) {
                    int br = wn*WN + p*16 + (lane & 15);
                    uint32_t bd = bbase + br*128 + (uint32_t)(((l*4 + cc) ^ (br & 7)) << 4);
                    LDSM4(b[l][p], bd);
                }
            #pragma unroll
            for (int mt = 0; mt < 2; mt++)
                #pragma unroll
                for (int nt = 0; nt < NT; nt++) {
                    int p = nt >> 1, o = nt & 1;
                    MMA16816(acc[mt][nt], a[0][mt], b[0][p][o], b[0][p][o + 2]); // Ah*Bh
                    MMA16816(acc[mt][nt], a[0][mt], b[1][p][o], b[1][p][o + 2]); // Ah*Bl
                    MMA16816(acc[mt][nt], a[1][mt], b[0][p][o], b[0][p][o + 2]); // Al*Bh
                }
        }
        __syncthreads();                    // all warps done reading stage i%3
        if (tid == 0 && i + 3 < NC) issue(i + 3);
    }

    int r4 = lane >> 2, cc2 = (lane & 3) * 2;
    #pragma unroll
    for (int mt = 0; mt < 2; mt++)
        #pragma unroll
        for (int nt = 0; nt < NT; nt++) {
            int n = bn + wn*WN + nt*8 + cc2;
            #pragma unroll
            for (int hf = 0; hf < 2; hf++) {
                int m = bm + wm*32 + mt*16 + r4 + hf*8;
                float v0 = acc[mt][nt][hf*2], v1 = acc[mt][nt][hf*2 + 1];
                if (EPI == 0) {
                    int t = m & (SEQ - 1);
                    int mw = (m & ~(SEQ - 1)) + (flip ? (SEQ - 1 - t) : t);
                    float2 v = {v0, v1};
                    if (n < DINNER) *(float2*)&g_xm[(size_t)mw*DINNER + n] = v;
                    else            *(float2*)&g_z [(size_t)mw*DINNER + n - DINNER] = v;
                } else if (EPI == 2) {
                    float2 v = {v0, v1};
                    *(float2*)&g_dbc[(size_t)m*64 + n] = v;
                } else {
                    int t = m & (SEQ - 1);
                    int grow = (m & ~(SEQ - 1)) + (flip ? (SEQ - 1 - t) : t);
                    float* dst = outp + (size_t)grow*DIM + n;
                    const float* add = flip ? dst : (xres + (size_t)grow*DIM + n);
                    float2 av = *(const float2*)add;
                    float2 v = {fmaf(0.5f, v0, av.x), fmaf(0.5f, v1, av.y)};
                    *(float2*)dst = v;
                }
            }
        }
}

// ---------------- layernorm -> w packed hi/lo ----------------
__global__ void ln_kernel(const float* __restrict__ x, const float* __restrict__ g,
                          const float* __restrict__ b) {
    int row = blockIdx.x;
    const float* xr = x + (size_t)row * DIM;
    int tid = threadIdx.x;
    float v0 = xr[tid], v1 = xr[tid + 256];
    float s = v0 + v1, qq = v0*v0 + v1*v1;
    __shared__ float ss[8], sq[8];
    #pragma unroll
    for (int o = 16; o > 0; o >>= 1) {
        s += __shfl_down_sync(FULLMASK, s, o);
        qq += __shfl_down_sync(FULLMASK, qq, o);
    }
    if ((tid & 31) == 0) { ss[tid >> 5] = s; sq[tid >> 5] = qq; }
    __syncthreads();
    __shared__ float mean_s, rstd_s;
    if (tid == 0) {
        float st = 0.f, qt = 0.f;
        #pragma unroll
        for (int i = 0; i < 8; i++) { st += ss[i]; qt += sq[i]; }
        float m = st / DIM;
        mean_s = m;
        rstd_s = rsqrtf(qt / DIM - m*m + 1e-5f);
    }
    __syncthreads();
    float m = mean_s, r = rstd_s;
    split_store_pk(g_w2, NTOK, row, tid,       (v0 - m)*r*g[tid]       + b[tid]);
    split_store_pk(g_w2, NTOK, row, tid + 256, (v1 - m)*r*g[tid + 256] + b[tid + 256]);
}

// ---------------- causal depthwise conv (k=4) + SiLU ----------------
__global__ void conv_kernel(const float* __restrict__ cw, const float* __restrict__ cb) {
    size_t idx = (size_t)blockIdx.x * blockDim.x + threadIdx.x;
    int d = (int)(idx & (DINNER-1));
    int t = (int)((idx >> 10) & (SEQ-1));
    size_t row = idx >> 10;
    float acc = cb[d];
    #pragma unroll
    for (int k = 0; k < DCONV; k++) {
        int ts = t + k - (DCONV-1);
        if (ts >= 0)
            acc = fmaf(g_xm[idx + (size_t)((long)k - (DCONV-1)) * DINNER], cw[k*DINNER + d], acc);
    }
    float sg = 1.f / (1.f + __expf(-acc));
    float v = acc * sg;
    g_xc[idx] = v;
    split_store_pk(g_xc2, NTOK, row, d, v);
}

// ---------------- dt GEMM (K=32) + bias + softplus ----------------
__global__ __launch_bounds__(1024) void dt_kernel(const float* __restrict__ dtw,
                                                  const float* __restrict__ dtb) {
    const int ROWS = 16;
    int m0 = blockIdx.x * ROWS;
    int n = threadIdx.x;
    __shared__ float s[ROWS][DTRANK];
    if (n < ROWS*DTRANK) {
        int r = n >> 5, k = n & 31;
        s[r][k] = g_dbc[(size_t)(m0+r)*64 + k];
    }
    __syncthreads();
    float w[32];
    #pragma unroll
    for (int k = 0; k < 32; k++) w[k] = dtw[k*DINNER + n];
    float bias = dtb[n];
    #pragma unroll 4
    for (int r = 0; r < ROWS; r++) {
        float acc = bias;
        #pragma unroll
        for (int k = 0; k < 32; k++) acc = fmaf(s[r][k], w[k], acc);
        float v = (acc > 20.f) ? acc : log1pf(__expf(acc));
        g_dt[(size_t)(m0+r)*DINNER + n] = v;
    }
}

// ---------------- selective scan + Dp skip + SiLU(z) gate -> y packed -------
template<bool FAST>
__device__ __forceinline__ void scan_body(size_t base, size_t rowbase, int d,
                                          const float* __restrict__ bcp,
                                          const float (&a)[16], float Dv, int lane,
                                          float (*sBC)[32]) {
    float pdt[4], px[4], pz[4];
    #pragma unroll
    for (int i = 0; i < 4; i++) {
        size_t off = base + (size_t)i * DINNER;
        pdt[i] = g_dt[off]; px[i] = g_xc[off]; pz[i] = g_z[off];
        sBC[i][lane] = bcp[(size_t)i * 64];
    }
    __syncwarp();
    uint64_t h[8];
    #pragma unroll
    for (int i = 0; i < 8; i++) h[i] = 0ull;

    for (int t0 = 0; t0 < SEQ; t0 += 4) {
        int sb = t0 & 4;
        #pragma unroll
        for (int u = 0; u < 4; u++) {
            int t = t0 + u;
            float dtv = pdt[u], xv = px[u], zv = pz[u];
            int tn = t + 4;
            if (tn < SEQ) {
                size_t offn = base + (size_t)tn * DINNER;
                pdt[u] = g_dt[offn]; px[u] = g_xc[offn]; pz[u] = g_z[offn];
                sBC[(sb ^ 4) + u][lane] = bcp[(size_t)tn * 64];
            }
            float dtx = dtv * xv;
            uint64_t dtxp; PACK2(dtxp, dtx, dtx);
            uint64_t rp, e2p;
            if (FAST) {
                float e1 = __expf(-dtv);
                float e2 = e1 * e1;
                PACK2(rp, e1, e2);
                PACK2(e2p, e2, e2);
            }
            uint64_t yp = 0ull;
            const uint64_t* bc2 = reinterpret_cast<const uint64_t*>(sBC[sb + u]);
            #pragma unroll
            for (int k = 0; k < 8; k++) {
                uint64_t rk;
                if (FAST) {
                    rk = rp;
                    if (k < 7) FMUL2(rp, rp, e2p);
                } else {
                    float rl = __expf(dtv * a[2*k]);
                    float rh = __expf(dtv * a[2*k + 1]);
                    PACK2(rk, rl, rh);
                }
                uint64_t bx; FMUL2(bx, dtxp, bc2[k]);
                FFMA2(h[k], rk, h[k], bx);
                FFMA2(yp, h[k], bc2[8 + k], yp);
            }
            float ylo, yhi; UNPACK2(ylo, yhi, yp);
            float yv = ylo + yhi;
            float sg = __fdividef(zv, 1.f + __expf(-zv));
            float yo = fmaf(xv, Dv, yv) * sg;
            split_store_pk(g_y2, NTOK, rowbase + t, d, yo);
        }
        __syncwarp();
    }
}

__global__ __launch_bounds__(32) void scan_kernel(const float* __restrict__ A_log,
                                                  const float* __restrict__ Dp) {
    __shared__ __align__(16) float sBC[8][32];
    int b = blockIdx.x;
    int lane = threadIdx.x;
    int d = blockIdx.y * 32 + lane;
    float a[16];
    bool fast = true;
    #pragma unroll
    for (int s = 0; s < 16; s++) {
        a[s] = -__expf(A_log[(size_t)d*DSTATE + s]);
        fast = fast && (fabsf(a[s] + (float)(s+1)) <= 1e-4f * (float)(s+1));
    }
    fast = __all_sync(FULLMASK, fast);
    float Dv = Dp[d];
    size_t rowbase = (size_t)b * SEQ;
    size_t base = rowbase * DINNER + d;
    const float* bcp = g_dbc + (size_t)b * SEQ * 64 + 32 + lane;
    if (fast) scan_body<true >(base, rowbase, d, bcp, a, Dv, lane, sBC);
    else      scan_body<false>(base, rowbase, d, bcp, a, Dv, lane, sBC);
}

// ---------------- launch ----------------
#define SMEM_MMA_128 (128 + 3 * (16384 + 16384))   // 98432
#define SMEM_MMA_64  (128 + 3 * (16384 + 8192))    // 73856

extern "C" void kernel_launch(void* const* d_in, const int* in_sizes, int n_in,
                              void* d_out, int out_size) {
    const float* x    = (const float*)d_in[0];
    const float* ln_g = (const float*)d_in[1];
    const float* ln_b = (const float*)d_in[2];

    cudaFuncSetAttribute(mma_gemm_kernel<128,0>, cudaFuncAttributeMaxDynamicSharedMemorySize, SMEM_MMA_128);
    cudaFuncSetAttribute(mma_gemm_kernel<128,1>, cudaFuncAttributeMaxDynamicSharedMemorySize, SMEM_MMA_128);
    cudaFuncSetAttribute(mma_gemm_kernel<64,2>,  cudaFuncAttributeMaxDynamicSharedMemorySize, SMEM_MMA_64);

    ln_kernel<<<NTOK, 256>>>(x, ln_g, ln_b);    // our launch 0

    for (int dir = 0; dir < 2; dir++) {
        const float* in_w    = (const float*)d_in[3 + 9*dir + 0];
        const float* conv_w  = (const float*)d_in[3 + 9*dir + 1];
        const float* conv_b  = (const float*)d_in[3 + 9*dir + 2];
        const float* xproj_w = (const float*)d_in[3 + 9*dir + 3];
        const float* dt_w    = (const float*)d_in[3 + 9*dir + 4];
        const float* dt_b    = (const float*)d_in[3 + 9*dir + 5];
        const float* A_log   = (const float*)d_in[3 + 9*dir + 6];
        const float* Dp      = (const float*)d_in[3 + 9*dir + 7];
        const float* out_w   = (const float*)d_in[3 + 9*dir + 8];

        split_w_kernel<<<dim3(2048/32, 512/32),  dim3(32,8)>>>(in_w, 512, 2048, 0);  // 1 (dir0)
        if (dir == 0) pad_kernel<<<1, 32>>>();                                       // 2 (dir0)
        // dir0: our launch 3 -> captured by ncu (-s 5 skips 2 harness + 3 ours)
        mma_gemm_kernel<128,0><<<dim3(2048/128, NTOK/128), 256, SMEM_MMA_128>>>(nullptr, nullptr, dir);
        conv_kernel<<<(NTOK*(size_t)DINNER)/256, 256>>>(conv_w, conv_b);
        split_w_kernel<<<dim3(64/32, 1024/32), dim3(32,8)>>>(xproj_w, 1024, 64, 2);
        mma_gemm_kernel<64,2><<<dim3(1, NTOK/128), 256, SMEM_MMA_64>>>(nullptr, nullptr, 0);
        dt_kernel<<<NTOK/16, 1024>>>(dt_w, dt_b);
        scan_kernel<<<dim3(BATCH, DINNER/32), 32>>>(A_log, Dp);
        split_w_kernel<<<dim3(512/32, 1024/32), dim3(32,8)>>>(out_w, 1024, 512, 1);
        mma_gemm_kernel<128,1><<<dim3(DIM/128, NTOK/128), 256, SMEM_MMA_128>>>(x, (float*)d_out, dir);
    }
}